// round 15
// baseline (speedup 1.0000x reference)
#include <cuda.h>
#include <cuda_runtime.h>
#include <cuda_bf16.h>
#include <cstdint>
#include <math.h>

// ---------------------------------------------------------------------------
// Problem constants
// ---------------------------------------------------------------------------
#define Bn   4
#define Sn   2048
#define En   768
#define DFFn 3072
#define MTOT (Bn * Sn)          // 8192
#define LNEPS 1e-5f

#if defined(__CUDA_ARCH__) && \
    (defined(__CUDA_ARCH_FEAT_SM103_ALL) || defined(__CUDA_ARCH_FEAT_SM100_ALL) || \
     defined(__CUDA_ARCH_FEAT_SM101_ALL) || \
     (defined(__CUDA_ARCH_SPECIFIC__)        && (__CUDA_ARCH_SPECIFIC__        >= 1000)) || \
     (defined(__CUDA_ARCH_FAMILY_SPECIFIC__) && (__CUDA_ARCH_FAMILY_SPECIFIC__ >= 1000)))
#define HAS_TC 1
#else
#define HAS_TC 0
#endif

typedef __nv_bfloat16 bf16;

// ---------------------------------------------------------------------------
// Scratch. bf16 operand tensors in SW64 PANEL layout: 128 rows x 32 cols per
// panel (8 KB, 64-byte rows), panel index = rowBlk*(kd/32) + kBlk.
// probs (g_ph/g_pl) and fp32 tensors stay row-major.
// ---------------------------------------------------------------------------
__device__ __align__(128) bf16  g_qh [MTOT * En],  g_ql [MTOT * En];
__device__ __align__(128) bf16  g_kh [MTOT * En],  g_kl [MTOT * En];
__device__ __align__(128) bf16  g_vth[MTOT * En],  g_vtl[MTOT * En];   // V^T panels [En, MTOT]
__device__ __align__(128) float g_s  [(size_t)Bn * Sn * Sn];           // raw scores
__device__ __align__(128) bf16  g_ph [(size_t)Bn * Sn * Sn];           // prob planes (row-major)
__device__ __align__(128) bf16  g_pl [(size_t)Bn * Sn * Sn];
__device__ __align__(128) bf16  g_hh [(size_t)MTOT * DFFn];            // MLP hidden panels
__device__ __align__(128) bf16  g_hl [(size_t)MTOT * DFFn];
__device__ __align__(128) float g_h  [MTOT * En];
__device__ __align__(128) float g_x1 [MTOT * En];
__device__ __align__(128) bf16  g_x1h[MTOT * En], g_x1l[MTOT * En];
__device__ __align__(128) float g_x2 [MTOT * En];
__device__ __align__(128) bf16  g_x2h[MTOT * En], g_x2l[MTOT * En];
__device__ __align__(128) float g_mlp[MTOT * En];
__device__ __align__(128) bf16  g_xh [MTOT * En], g_xl [MTOT * En];
__device__ __align__(128) bf16  g_kvh[MTOT * En], g_kvl[MTOT * En];
__device__ __align__(128) bf16  g_wh [6 * En * En + 2 * DFFn * En];
__device__ __align__(128) bf16  g_wl [6 * En * En + 2 * DFFn * En];

// ---------------------------------------------------------------------------
// SW64 panel addressing: panel 128 rows x 32 cols, 64-byte rows.
// ---------------------------------------------------------------------------
__device__ __forceinline__ long panel_off(int row, int col, int kd) {
    long p = (long)(row >> 7) * (kd >> 5) + (col >> 5);
    uint32_t b = (uint32_t)((row & 127) * 64 + (col & 31) * 2);
    b ^= (b >> 3) & 0x30;
    return p * 8192 + b;
}

__device__ __forceinline__ uint32_t smem_u32(const void* p) {
    uint32_t a;
    asm("{ .reg .u64 t; cvta.to.shared.u64 t, %1; cvt.u32.u64 %0, t; }"
        : "=r"(a) : "l"(p));
    return a;
}

__device__ __forceinline__ void bf16_split(float x, bf16& h, bf16& l) {
    h = __float2bfloat16_rn(x);
    l = __float2bfloat16_rn(x - __bfloat162float(h));
}

__device__ __forceinline__ uint32_t pack2(bf16 a, bf16 b) {
    __nv_bfloat162 t(a, b);
    return *(uint32_t*)&t;
}

__device__ __forceinline__ float panel_read(const bf16* p, int row, int col, int kd) {
    return __bfloat162float(*(const bf16*)((const char*)p + panel_off(row, col, kd)));
}

#if HAS_TC
__device__ __forceinline__ uint32_t elect_one() {
    uint32_t pred;
    asm volatile("{\n\t.reg .pred p;\n\telect.sync _|p, 0xFFFFFFFF;\n\t"
                 "selp.b32 %0, 1, 0, p;\n\t}" : "=r"(pred));
    return pred;
}

#define MBARRIER_INIT(addr, cnt) \
    asm volatile("mbarrier.init.shared.b64 [%0], %1;" :: "r"(addr), "r"(cnt) : "memory")

#define MBARRIER_EXPECT_TX(addr, bytes) \
    asm volatile("mbarrier.arrive.expect_tx.shared.b64 _, [%0], %1;" \
                 :: "r"((uint32_t)(addr)), "r"((uint32_t)(bytes)) : "memory")

#define MBARRIER_WAIT_PARITY(mbar_addr, phase_parity) do {                          \
    uint32_t _mbar = (uint32_t)(mbar_addr);                                         \
    uint32_t _par  = (uint32_t)(phase_parity);                                      \
    uint32_t _done;                                                                 \
    asm volatile("{\n\t.reg .pred p;\n\t"                                           \
        "mbarrier.try_wait.parity.acquire.cta.shared::cta.b64 p, [%1], %2;\n\t"     \
        "selp.b32 %0, 1, 0, p;\n\t}"                                                \
        : "=r"(_done) : "r"(_mbar), "r"(_par) : "memory");                          \
    if (!_done) {                                                                   \
        asm volatile("{\n\t.reg .pred P1;\n\t"                                      \
        "WAIT_LOOP_%=:\n\t"                                                         \
        "mbarrier.try_wait.parity.acquire.cta.shared::cta.b64 P1, [%0], %1, 0x989680;\n\t" \
        "@P1 bra.uni WAIT_DONE_%=;\n\t"                                             \
        "bra.uni WAIT_LOOP_%=;\n\t"                                                 \
        "WAIT_DONE_%=:\n\t}"                                                        \
        :: "r"(_mbar), "r"(_par) : "memory");                                       \
    }                                                                               \
} while (0)

#define TCGEN05_ALLOC(smem_res, ncols) \
    asm volatile("tcgen05.alloc.cta_group::1.sync.aligned.shared::cta.b32 [%0], %1;" \
                 :: "r"((uint32_t)(smem_res)), "r"((uint32_t)(ncols)) : "memory")
#define TCGEN05_DEALLOC(tmem, ncols) \
    asm volatile("tcgen05.dealloc.cta_group::1.sync.aligned.b32 %0, %1;" \
                 :: "r"(tmem), "r"((uint32_t)(ncols)))
#define TCGEN05_RELINQUISH() \
    asm volatile("tcgen05.relinquish_alloc_permit.cta_group::1.sync.aligned;")
#define TCGEN05_COMMIT(mbar) \
    asm volatile("tcgen05.commit.cta_group::1.mbarrier::arrive::one.shared::cluster.b64 [%0];" \
                 :: "r"((uint32_t)(mbar)) : "memory")
#define TCGEN05_FENCE_AFTER() \
    asm volatile("tcgen05.fence::after_thread_sync;" ::: "memory")
#define TCGEN05_FENCE_BEFORE() \
    asm volatile("tcgen05.fence::before_thread_sync;" ::: "memory")
#define TCGEN05_WAIT_LD() \
    asm volatile("tcgen05.wait::ld.sync.aligned;" ::: "memory")

#define BULK_LOAD(dst, src, bytes, mbar) \
    asm volatile("cp.async.bulk.shared::cluster.global.mbarrier::complete_tx::bytes " \
                 "[%0], [%1], %2, [%3];" \
                 :: "r"((uint32_t)(dst)), "l"(src), "r"((uint32_t)(bytes)), \
                    "r"((uint32_t)(mbar)) : "memory")

#define TMA_LOAD_2D(smem_addr, map, cx, cy, mbar) \
    asm volatile( \
        "cp.async.bulk.tensor.2d.shared::cta.global.tile.mbarrier::complete_tx::bytes " \
        "[%0], [%1, {%2, %3}], [%4];" \
        :: "r"((uint32_t)(smem_addr)), "l"(map), "r"((int)(cx)), "r"((int)(cy)), \
           "r"((uint32_t)(mbar)) : "memory")

#define TCGEN05_LD_32X32B_X32(r, tmem_addr) \
    asm volatile( \
        "tcgen05.ld.sync.aligned.32x32b.x32.b32 " \
        "{%0, %1, %2, %3, %4, %5, %6, %7, " \
        " %8, %9, %10, %11, %12, %13, %14, %15, " \
        " %16, %17, %18, %19, %20, %21, %22, %23, " \
        " %24, %25, %26, %27, %28, %29, %30, %31}, [%32];" \
        : "=r"((r)[0]),  "=r"((r)[1]),  "=r"((r)[2]),  "=r"((r)[3]), \
          "=r"((r)[4]),  "=r"((r)[5]),  "=r"((r)[6]),  "=r"((r)[7]), \
          "=r"((r)[8]),  "=r"((r)[9]),  "=r"((r)[10]), "=r"((r)[11]), \
          "=r"((r)[12]), "=r"((r)[13]), "=r"((r)[14]), "=r"((r)[15]), \
          "=r"((r)[16]), "=r"((r)[17]), "=r"((r)[18]), "=r"((r)[19]), \
          "=r"((r)[20]), "=r"((r)[21]), "=r"((r)[22]), "=r"((r)[23]), \
          "=r"((r)[24]), "=r"((r)[25]), "=r"((r)[26]), "=r"((r)[27]), \
          "=r"((r)[28]), "=r"((r)[29]), "=r"((r)[30]), "=r"((r)[31]) \
        : "r"(tmem_addr))

// SW64 K-major smem descriptor (validated in R13).
__device__ __forceinline__ uint64_t make_desc(uint32_t addr) {
    constexpr uint64_t base =
        (uint64_t(4)  << 61) | (uint64_t(1) << 46) |
        (uint64_t(32) << 32) | (uint64_t(1) << 16);
    return base | ((uint64_t)(addr >> 4) & 0x3FFF);
}

__device__ __forceinline__ void mma_bf16(uint32_t d_tmem, uint64_t da, uint64_t db,
                                         uint32_t idesc, uint32_t acc) {
    asm volatile(
        "{\n\t.reg .pred p;\n\tsetp.ne.u32 p, %4, 0;\n\t"
        "tcgen05.mma.cta_group::1.kind::f16 [%0], %1, %2, %3, {%5, %5, %5, %5}, p;\n\t}"
        :: "r"(d_tmem), "l"(da), "l"(db), "r"(idesc), "r"(acc), "r"(0u)
        : "memory");
}
#endif  // HAS_TC

// ---------------------------------------------------------------------------
// GEMM (NT): C = A * B^T, bf16 (hi,lo) planes, 3-pass. Tiles BM=128, BN=256,
// BK=32. 2-stage mbarrier ring (stage 48KB) -> 99KB smem/CTA so TWO CTAs
// co-reside per SM (TMEM 256 cols each = 512 total). Cross-CTA overlap hides
// per-chunk fixed latencies (wait wakeup, commit->arrive, epilogue tail).
//   EPI 0:+bias[n] 1:relu(+bias[n]) 2:*scale 3:+bias[m] 4:none
//   OUT 0: fp32 row-major C   1: bf16 panel planes (Ch, Cl)
//   causal 0:none 1:skip upper tiles 2:K-limit (causal PV)
//   LOADA 1: A via 2D TMA SW64 (row-major probs); else A panels via bulk copy.
// ---------------------------------------------------------------------------
static constexpr int SM_TILE0  = 1024;
static constexpr int SM_A_HI   = 0;          // 128x32 bf16 = 8 KB
static constexpr int SM_A_LO   = 8192;
static constexpr int SM_B_HI   = 16384;      // 256x32 bf16 = 16 KB (2 panels)
static constexpr int SM_B_LO   = 32768;
static constexpr int SM_STAGE  = 49152;
static constexpr int GEMM_SMEM = SM_TILE0 + 2 * SM_STAGE;   // 99328 B
static constexpr uint32_t IDESC_BF16 =
    (1u << 4) | (1u << 7) | (1u << 10) | ((256u / 8u) << 17) | ((128u / 16u) << 24);

// Control smem: 0 = tmem ptr, empty[s] = 8+s*8 (s<2), full[s] = 32+s*8.
template<int EPI, int OUT, int LOADA>
__global__ void __launch_bounds__(256, 2)
gemm_tc(const __grid_constant__ CUtensorMap tmAh,
        const __grid_constant__ CUtensorMap tmAl,
        const bf16* __restrict__ Aph, const bf16* __restrict__ Apl,
        const bf16* __restrict__ Bph, const bf16* __restrict__ Bpl,
        const float* __restrict__ bias,
        float* __restrict__ C, bf16* __restrict__ Ch, bf16* __restrict__ Cl,
        int K, int KAB, int KBB, int ldc,
        int aYoff, int bXoff, int bYoff, long sC, float scale, int causal)
{
    extern __shared__ __align__(1024) char smem[];
    const int tid = threadIdx.x;

    const int rm = blockIdx.y * 128;
    const int cn = blockIdx.x * 256;
    if (causal == 1 && cn > rm + 127) return;

    if (OUT == 0) C += (long)blockIdx.z * sC;

    int Keff = K;
    if (causal == 2) Keff = min(K, rm + 128);

#if HAS_TC
    const uint32_t smem_base = smem_u32(smem);
    const int wid = tid >> 5;

    if (tid == 0) {
#pragma unroll
        for (int s = 0; s < 2; s++) {
            MBARRIER_INIT(smem_base + 8 + s * 8, 1);    // empty[s]
            MBARRIER_INIT(smem_base + 32 + s * 8, 1);   // full[s]
        }
    }
    if (wid == 5) TCGEN05_ALLOC(smem_base + 0, 256);
    __syncthreads();

    uint32_t tmem;
    asm volatile("ld.shared.b32 %0, [%1];" : "=r"(tmem) : "r"(smem_base));

    const int NC = Keff >> 5;                 // BK = 32
    const int ay  = blockIdx.z * aYoff + rm;  // TMA row (LOADA=1)
    const long aP = ((long)((blockIdx.z * aYoff + rm) >> 7)) * KAB;
    const long bP0 = ((long)((blockIdx.z * bYoff + cn) >> 7)) * KBB;
    const long bP1 = bP0 + KBB;
    const int  kB0 = (blockIdx.z * bXoff) >> 5;

    if (wid == 4 && elect_one()) {
        // ---------------- producer (single thread) ----------------
        for (int c = 0; c < NC; c++) {
            const int s = c & 1;
            if (c >= 2)  // stage s still owned by MMA of chunk c-2
                MBARRIER_WAIT_PARITY(smem_base + 8 + s * 8, ((c >> 1) + 1) & 1);
            const uint32_t fullb = smem_base + 32 + s * 8;
            MBARRIER_EXPECT_TX(fullb, (uint32_t)SM_STAGE);
            const uint32_t tn = smem_base + SM_TILE0 + s * SM_STAGE;
            if (LOADA == 1) {
                const int kx = c << 5;
                TMA_LOAD_2D(tn + SM_A_HI, &tmAh, kx, ay, fullb);
                TMA_LOAD_2D(tn + SM_A_LO, &tmAl, kx, ay, fullb);
            } else {
                const long pa = (aP + c) * 8192;
                BULK_LOAD(tn + SM_A_HI, (const char*)Aph + pa, 8192, fullb);
                BULK_LOAD(tn + SM_A_LO, (const char*)Apl + pa, 8192, fullb);
            }
            const long pb0 = (bP0 + kB0 + c) * 8192;
            const long pb1 = (bP1 + kB0 + c) * 8192;
            BULK_LOAD(tn + SM_B_HI,        (const char*)Bph + pb0, 8192, fullb);
            BULK_LOAD(tn + SM_B_HI + 8192, (const char*)Bph + pb1, 8192, fullb);
            BULK_LOAD(tn + SM_B_LO,        (const char*)Bpl + pb0, 8192, fullb);
            BULK_LOAD(tn + SM_B_LO + 8192, (const char*)Bpl + pb1, 8192, fullb);
        }
    } else if (wid == 5 && elect_one()) {
        // ---------------- MMA consumer (single thread) ----------------
        for (int c = 0; c < NC; c++) {
            const int s = c & 1;
            MBARRIER_WAIT_PARITY(smem_base + 32 + s * 8, (c >> 1) & 1);
            const uint32_t tb = smem_base + SM_TILE0 + s * SM_STAGE;
            const uint64_t dah = make_desc(tb + SM_A_HI);
            const uint64_t dal = make_desc(tb + SM_A_LO);
            const uint64_t dbh = make_desc(tb + SM_B_HI);
            const uint64_t dbl = make_desc(tb + SM_B_LO);
#pragma unroll
            for (int st = 0; st < 2; st++)       // hi*hi  (K=16 per step)
                mma_bf16(tmem, dah + st * 2, dbh + st * 2, IDESC_BF16,
                         (c == 0 && st == 0) ? 0u : 1u);
#pragma unroll
            for (int st = 0; st < 2; st++)       // hi*lo
                mma_bf16(tmem, dah + st * 2, dbl + st * 2, IDESC_BF16, 1u);
#pragma unroll
            for (int st = 0; st < 2; st++)       // lo*hi
                mma_bf16(tmem, dal + st * 2, dbh + st * 2, IDESC_BF16, 1u);
            TCGEN05_COMMIT(smem_base + 8 + s * 8);
        }
    }
    // Gate idle/epilogue warps so the tile-final parity wait is unambiguous.
    __syncthreads();

    const int cL = NC - 1;
    MBARRIER_WAIT_PARITY(smem_base + 8 + (cL & 1) * 8, (cL >> 1) & 1);
    TCGEN05_FENCE_AFTER();

    if (wid < 4) {
        const int lane = tid & 31;
        const int m = rm + wid * 32 + lane;
        const float biasm = (EPI == 3) ? bias[m] : 0.f;
#pragma unroll
        for (int seg = 0; seg < 8; seg++) {
            uint32_t r[32];
            TCGEN05_LD_32X32B_X32(r, tmem + seg * 32);
            TCGEN05_WAIT_LD();
#pragma unroll
            for (int j = 0; j < 32; j += 4) {
                float v[4];
#pragma unroll
                for (int tt = 0; tt < 4; tt++) {
                    const int n = cn + seg * 32 + j + tt;
                    float x = __uint_as_float(r[j + tt]);
                    if (EPI == 0)      x += bias[n];
                    else if (EPI == 1) x = fmaxf(x + bias[n], 0.f);
                    else if (EPI == 2) x *= scale;
                    else if (EPI == 3) x += biasm;
                    v[tt] = x;
                }
                if (OUT == 0) {
                    *(float4*)(C + (long)m * ldc + cn + seg * 32 + j) =
                        make_float4(v[0], v[1], v[2], v[3]);
                } else {
                    bf16 h0, l0, h1, l1, h2, l2, h3, l3;
                    bf16_split(v[0], h0, l0); bf16_split(v[1], h1, l1);
                    bf16_split(v[2], h2, l2); bf16_split(v[3], h3, l3);
                    const long off = panel_off(m, cn + seg * 32 + j, ldc);
                    uint2 uh, ul;
                    uh.x = pack2(h0, h1); uh.y = pack2(h2, h3);
                    ul.x = pack2(l0, l1); ul.y = pack2(l2, l3);
                    *(uint2*)((char*)Ch + off) = uh;
                    *(uint2*)((char*)Cl + off) = ul;
                }
            }
        }
        TCGEN05_FENCE_BEFORE();
    }
    __syncthreads();
    if (wid == 5) {
        TCGEN05_RELINQUISH();
        TCGEN05_DEALLOC(tmem, 256);
    }
#else
    // --------------------- SIMT fp32 fallback path -------------------------
    constexpr int BK = 16;
    float (*As)[132] = (float (*)[132])(smem);
    float (*Bs)[132] = (float (*)[132])(smem + BK * 132 * sizeof(float));
    const int tx = tid & 15, ty = tid >> 4;
    const int lda = KAB * 32, ldbK = KBB * 32;

    for (int half = 0; half < 2; half++) {
        const int cnh = cn + half * 128;
        float acc[8][8];
#pragma unroll
        for (int i = 0; i < 8; i++)
#pragma unroll
            for (int j = 0; j < 8; j++) acc[i][j] = 0.f;

        for (int k0 = 0; k0 < Keff; k0 += BK) {
#pragma unroll
            for (int i = 0; i < 2; i++) {
                const int q = i * 256 + tid;
                const int row = q >> 1, kc = (q & 1) * 8;
#pragma unroll
                for (int u = 0; u < 8; u++) {
                    const int k = k0 + kc + u;
                    float av;
                    if (LOADA == 1) {
                        const long ai = (long)(blockIdx.z * aYoff + rm + row) * lda + k;
                        av = __bfloat162float(Aph[ai]) + __bfloat162float(Apl[ai]);
                    } else {
                        const int gr = blockIdx.z * aYoff + rm + row;
                        av = panel_read(Aph, gr, k, lda) + panel_read(Apl, gr, k, lda);
                    }
                    const int gbr = blockIdx.z * bYoff + cnh + row;
                    const int gbk = blockIdx.z * bXoff + k;
                    As[kc + u][row] = av;
                    Bs[kc + u][row] = panel_read(Bph, gbr, gbk, ldbK) +
                                      panel_read(Bpl, gbr, gbk, ldbK);
                }
            }
            __syncthreads();
#pragma unroll
            for (int kk = 0; kk < BK; kk++) {
                float a[8], b[8];
#pragma unroll
                for (int i = 0; i < 8; i++) a[i] = As[kk][ty * 8 + i];
#pragma unroll
                for (int j = 0; j < 8; j++) b[j] = Bs[kk][tx * 8 + j];
#pragma unroll
                for (int i = 0; i < 8; i++)
#pragma unroll
                    for (int j = 0; j < 8; j++) acc[i][j] += a[i] * b[j];
            }
            __syncthreads();
        }

#pragma unroll
        for (int i = 0; i < 8; i++) {
            const int m = rm + ty * 8 + i;
            const float biasm = (EPI == 3) ? bias[m] : 0.f;
#pragma unroll
            for (int j = 0; j < 8; j++) {
                const int n = cnh + tx * 8 + j;
                float x = acc[i][j];
                if (EPI == 0)      x += bias[n];
                else if (EPI == 1) x = fmaxf(x + bias[n], 0.f);
                else if (EPI == 2) x *= scale;
                else if (EPI == 3) x += biasm;
                if (OUT == 0) C[(long)m * ldc + n] = x;
                else {
                    bf16 hh, ll;
                    bf16_split(x, hh, ll);
                    const long off = panel_off(m, n, ldc);
                    *(bf16*)((char*)Ch + off) = hh;
                    *(bf16*)((char*)Cl + off) = ll;
                }
            }
        }
        __syncthreads();
    }
#endif
}

// ---------------------------------------------------------------------------
// Elementwise bf16 Dekker split -> SW64 PANEL layout. Two tensors per launch.
// ---------------------------------------------------------------------------
__device__ __forceinline__ void split_body(const float* __restrict__ src,
                                           bf16* __restrict__ hi,
                                           bf16* __restrict__ lo, long n4, int kd)
{
    for (long i = blockIdx.x * 256L + threadIdx.x; i < n4; i += (long)gridDim.x * 256) {
        const float4 f = *(const float4*)(src + i * 4);
        bf16 h0, l0, h1, l1, h2, l2, h3, l3;
        bf16_split(f.x, h0, l0); bf16_split(f.y, h1, l1);
        bf16_split(f.z, h2, l2); bf16_split(f.w, h3, l3);
        const long e0 = i * 4;
        const int row = (int)(e0 / kd);
        const int col = (int)(e0 - (long)row * kd);
        const long off = panel_off(row, col, kd);
        uint2 uh, ul;
        uh.x = pack2(h0, h1); uh.y = pack2(h2, h3);
        ul.x = pack2(l0, l1); ul.y = pack2(l2, l3);
        *(uint2*)((char*)hi + off) = uh;
        *(uint2*)((char*)lo + off) = ul;
    }
}

__global__ void __launch_bounds__(256)
split2_k(const float* __restrict__ s0, bf16* __restrict__ h0, bf16* __restrict__ l0,
         const float* __restrict__ s1, bf16* __restrict__ h1, bf16* __restrict__ l1,
         long n4, int kd0, int kd1)
{
    if (blockIdx.y == 0) split_body(s0, h0, l0, n4, kd0);
    else                 split_body(s1, h1, l1, n4, kd1);
}

// ---------------------------------------------------------------------------
// Row softmax over fp32 scores -> bf16 (hi, lo) prob planes (row-major).
// ---------------------------------------------------------------------------
__global__ void __launch_bounds__(256)
softmax_k(const float* __restrict__ S, bf16* __restrict__ Ph,
          bf16* __restrict__ Pl, int causal)
{
    const int row = blockIdx.x;
    const int b = row >> 11;
    const int i = row & 2047;
    const float* p = S + (long)b * Sn * Sn + (long)i * Sn;
    bf16* ph = Ph + (long)b * Sn * Sn + (long)i * Sn;
    bf16* pl = Pl + (long)b * Sn * Sn + (long)i * Sn;
    const int L = causal ? (i + 1) : Sn;
    const int FILL = causal ? (((i >> 7) + 1) << 7) : Sn;
    const int tid = threadIdx.x;
    __shared__ float sh[8];

    float m = -3.4e38f;
    for (int j = tid; j < L; j += 256) m = fmaxf(m, p[j]);
#pragma unroll
    for (int o = 16; o > 0; o >>= 1) m = fmaxf(m, __shfl_xor_sync(~0u, m, o));
    if ((tid & 31) == 0) sh[tid >> 5] = m;
    __syncthreads();
    m = sh[0];
#pragma unroll
    for (int w = 1; w < 8; w++) m = fmaxf(m, sh[w]);

    float s = 0.f;
    for (int j = tid; j < L; j += 256) s += __expf(p[j] - m);
#pragma unroll
    for (int o = 16; o > 0; o >>= 1) s += __shfl_xor_sync(~0u, s, o);
    __syncthreads();
    if ((tid & 31) == 0) sh[tid >> 5] = s;
    __syncthreads();
    s = 0.f;
#pragma unroll
    for (int w = 0; w < 8; w++) s += sh[w];
    const float inv = 1.f / s;

    for (int j = tid; j < L; j += 256) {
        const float v = __expf(p[j] - m) * inv;
        bf16 hh, ll;
        bf16_split(v, hh, ll);
        ph[j] = hh;
        pl[j] = ll;
    }
    const bf16 z = __float2bfloat16(0.f);
    for (int j = L + tid; j < FILL; j += 256) { ph[j] = z; pl[j] = z; }
}

// ---------------------------------------------------------------------------
// y = LayerNorm(x + h) * g + b; optional SW64-panel bf16 splits (yh, yl).
// ---------------------------------------------------------------------------
__global__ void __launch_bounds__(256)
add_ln_k(const float* __restrict__ x, const float* __restrict__ h,
         const float* __restrict__ g, const float* __restrict__ bt,
         float* __restrict__ y, bf16* __restrict__ yh, bf16* __restrict__ yl)
{
    const long row = blockIdx.x;
    const float* xr = x + row * En;
    const float* hr = h + row * En;
    const int tid = threadIdx.x;

    float v[3];
    float s = 0.f, s2 = 0.f;
#pragma unroll
    for (int t = 0; t < 3; t++) {
        const int c = tid + t * 256;
        const float u = xr[c] + hr[c];
        v[t] = u;
        s += u;
        s2 += u * u;
    }
    __shared__ float shA[8], shB[8];
#pragma unroll
    for (int o = 16; o > 0; o >>= 1) {
        s  += __shfl_xor_sync(~0u, s,  o);
        s2 += __shfl_xor_sync(~0u, s2, o);
    }
    if ((tid & 31) == 0) { shA[tid >> 5] = s; shB[tid >> 5] = s2; }
    __syncthreads();
    s = 0.f; s2 = 0.f;
#pragma unroll
    for (int w = 0; w < 8; w++) { s += shA[w]; s2 += shB[w]; }

    const float mu   = s * (1.f / En);
    const float var  = s2 * (1.f / En) - mu * mu;
    const float rstd = rsqrtf(var + LNEPS);
#pragma unroll
    for (int t = 0; t < 3; t++) {
        const int c = tid + t * 256;
        const float o = (v[t] - mu) * rstd * g[c] + bt[c];
        y[row * En + c] = o;
        if (yh) {
            bf16 hh, ll;
            bf16_split(o, hh, ll);
            const long off = panel_off((int)row, c, En);
            *(bf16*)((char*)yh + off) = hh;
            *(bf16*)((char*)yl + off) = ll;
        }
    }
}

// ---------------------------------------------------------------------------
// Host: tensor-map encoding (probs only; SW64, box {32, boxRows}).
// ---------------------------------------------------------------------------
typedef CUresult (*PFN_tmEncode)(
    CUtensorMap*, CUtensorMapDataType, cuuint32_t, void*,
    const cuuint64_t*, const cuuint64_t*, const cuuint32_t*, const cuuint32_t*,
    CUtensorMapInterleave, CUtensorMapSwizzle, CUtensorMapL2promotion,
    CUtensorMapFloatOOBfill);

static PFN_tmEncode tm_encoder() {
    static PFN_tmEncode fn = nullptr;
    if (!fn) {
        void* p = nullptr;
        cudaDriverEntryPointQueryResult st;
#if CUDART_VERSION >= 12050
        cudaGetDriverEntryPointByVersion("cuTensorMapEncodeTiled", &p, 12000,
                                         cudaEnableDefault, &st);
#else
        cudaGetDriverEntryPoint("cuTensorMapEncodeTiled", &p,
                                cudaEnableDefault, &st);
#endif
        fn = (PFN_tmEncode)p;
    }
    return fn;
}

static CUtensorMap make_map(const void* base, long rowElems, long nRows, int boxRows)
{
    CUtensorMap m;
    cuuint64_t dims[2]    = {(cuuint64_t)rowElems, (cuuint64_t)nRows};
    cuuint64_t strides[1] = {(cuuint64_t)rowElems * 2};
    cuuint32_t box[2]     = {32u, (cuuint32_t)boxRows};
    cuuint32_t es[2]      = {1u, 1u};
    tm_encoder()(&m, CU_TENSOR_MAP_DATA_TYPE_BFLOAT16, 2, (void*)base,
                 dims, strides, box, es,
                 CU_TENSOR_MAP_INTERLEAVE_NONE, CU_TENSOR_MAP_SWIZZLE_64B,
                 CU_TENSOR_MAP_L2_PROMOTION_L2_128B,
                 CU_TENSOR_MAP_FLOAT_OOB_FILL_NONE);
    return m;
}

// ---------------------------------------------------------------------------
// Host launcher
// ---------------------------------------------------------------------------
extern "C" void kernel_launch(void* const* d_in, const int* in_sizes, int n_in,
                              void* d_out, int out_size)
{
    const float* x     = (const float*)d_in[0];
    const float* kv    = (const float*)d_in[1];
    const float* wq_w  = (const float*)d_in[2];
    const float* wq_b  = (const float*)d_in[3];
    const float* wk_w  = (const float*)d_in[4];
    const float* wk_b  = (const float*)d_in[5];
    const float* wv_w  = (const float*)d_in[6];
    const float* wv_b  = (const float*)d_in[7];
    const float* ln1_g = (const float*)d_in[8];
    const float* ln1_b = (const float*)d_in[9];
    const float* wq2_w = (const float*)d_in[10];
    const float* wq2_b = (const float*)d_in[11];
    const float* wk2_w = (const float*)d_in[12];
    const float* wk2_b = (const float*)d_in[13];
    const float* wv2_w = (const float*)d_in[14];
    const float* wv2_b = (const float*)d_in[15];
    const float* ln2_g = (const float*)d_in[16];
    const float* ln2_b = (const float*)d_in[17];
    const float* w1    = (const float*)d_in[18];
    const float* b1    = (const float*)d_in[19];
    const float* w2    = (const float*)d_in[20];
    const float* b2    = (const float*)d_in[21];
    const float* ln3_g = (const float*)d_in[22];
    const float* ln3_b = (const float*)d_in[23];
    float* out = (float*)d_out;

    bf16 *qh, *ql, *kh, *kl, *vth, *vtl, *prh, *prl, *hh, *hl;
    bf16 *x1h, *x1l, *x2h, *x2l, *xh, *xl, *kvh, *kvl, *wh, *wl;
    float *ps, *phf, *x1, *x2, *pmlp;
    cudaGetSymbolAddress((void**)&qh,  g_qh);   cudaGetSymbolAddress((void**)&ql,  g_ql);
    cudaGetSymbolAddress((void**)&kh,  g_kh);   cudaGetSymbolAddress((void**)&kl,  g_kl);
    cudaGetSymbolAddress((void**)&vth, g_vth);  cudaGetSymbolAddress((void**)&vtl, g_vtl);
    cudaGetSymbolAddress((void**)&prh, g_ph);   cudaGetSymbolAddress((void**)&prl, g_pl);
    cudaGetSymbolAddress((void**)&hh,  g_hh);   cudaGetSymbolAddress((void**)&hl,  g_hl);
    cudaGetSymbolAddress((void**)&x1h, g_x1h);  cudaGetSymbolAddress((void**)&x1l, g_x1l);
    cudaGetSymbolAddress((void**)&x2h, g_x2h);  cudaGetSymbolAddress((void**)&x2l, g_x2l);
    cudaGetSymbolAddress((void**)&xh,  g_xh);   cudaGetSymbolAddress((void**)&xl,  g_xl);
    cudaGetSymbolAddress((void**)&kvh, g_kvh);  cudaGetSymbolAddress((void**)&kvl, g_kvl);
    cudaGetSymbolAddress((void**)&wh,  g_wh);   cudaGetSymbolAddress((void**)&wl,  g_wl);
    cudaGetSymbolAddress((void**)&ps,  g_s);
    cudaGetSymbolAddress((void**)&phf, g_h);
    cudaGetSymbolAddress((void**)&x1,  g_x1);
    cudaGetSymbolAddress((void**)&x2,  g_x2);
    cudaGetSymbolAddress((void**)&pmlp, g_mlp);

    const long oWQ = 0, oWK = oWQ + (long)En * En, oWV = oWK + (long)En * En;
    const long oWQ2 = oWV + (long)En * En, oWK2 = oWQ2 + (long)En * En;
    const long oWV2 = oWK2 + (long)En * En;
    const long oW1 = oWV2 + (long)En * En, oW2 = oW1 + (long)DFFn * En;

    cudaFuncSetAttribute(gemm_tc<0,1,0>, cudaFuncAttributeMaxDynamicSharedMemorySize, GEMM_SMEM);
    cudaFuncSetAttribute(gemm_tc<3,1,0>, cudaFuncAttributeMaxDynamicSharedMemorySize, GEMM_SMEM);
    cudaFuncSetAttribute(gemm_tc<2,0,0>, cudaFuncAttributeMaxDynamicSharedMemorySize, GEMM_SMEM);
    cudaFuncSetAttribute(gemm_tc<4,0,1>, cudaFuncAttributeMaxDynamicSharedMemorySize, GEMM_SMEM);
    cudaFuncSetAttribute(gemm_tc<1,1,0>, cudaFuncAttributeMaxDynamicSharedMemorySize, GEMM_SMEM);
    cudaFuncSetAttribute(gemm_tc<1,0,0>, cudaFuncAttributeMaxDynamicSharedMemorySize, GEMM_SMEM);

    const float scale = 0.03608439182435161f;  // 1/sqrt(768)
    const long sSS = (long)Sn * Sn;
    const long sQE = (long)Sn * En;

    const dim3 gProj(En / 256, MTOT / 128, 1);
    const dim3 gVT(MTOT / 256, En / 128, 1);
    const dim3 gScore(Sn / 256, Sn / 128, Bn);
    const dim3 gPV(En / 256, Sn / 128, Bn);
    const dim3 gFF1(DFFn / 256, MTOT / 128, 1);
    const dim3 gFF2(En / 256, MTOT / 128, 1);

    const long nXY = (long)MTOT * En / 4;
    const long nW  = (long)En * En / 4;
    const long nFF = (long)DFFn * En / 4;

    CUtensorMap mPh = make_map(prh, Sn, MTOT, 128);
    CUtensorMap mPl = make_map(prl, Sn, MTOT, 128);

    // KAB/KBB = panels per 128-row block = kd/32.
    // Launch order keeps the causal score GEMM at index 5 (ncu -s 5 -c 1).
    split2_k<<<dim3(296, 2), 256>>>(x, xh, xl, kv, kvh, kvl, nXY, En, En);
    split2_k<<<dim3(148, 2), 256>>>(wq_w, wh + oWQ, wl + oWQ,
                                    wk_w, wh + oWK, wl + oWK, nW, En, En);
    gemm_tc<0,1,0><<<gProj, 256, GEMM_SMEM>>>(mPh, mPl, xh, xl, wh + oWQ, wl + oWQ,
        wq_b, nullptr, qh, ql, En, 24, 24, En, 0, 0, 0, 0, 1.f, 0);
    gemm_tc<0,1,0><<<gProj, 256, GEMM_SMEM>>>(mPh, mPl, xh, xl, wh + oWK, wl + oWK,
        wk_b, nullptr, kh, kl, En, 24, 24, En, 0, 0, 0, 0, 1.f, 0);
    split2_k<<<dim3(148, 2), 256>>>(wv_w,  wh + oWV,  wl + oWV,
                                    wv2_w, wh + oWV2, wl + oWV2, nW, En, En);
    // 5: causal score GEMM  <-- profiled launch
    gemm_tc<2,0,0><<<gScore, 256, GEMM_SMEM>>>(mPh, mPl, qh, ql, kh, kl,
        nullptr, ps, nullptr, nullptr, En, 24, 24, Sn, Sn, 0, Sn, sSS, scale, 1);
    gemm_tc<3,1,0><<<gVT, 256, GEMM_SMEM>>>(mPh, mPl, wh + oWV, wl + oWV, xh, xl,
        wv_b, nullptr, vth, vtl, En, 24, 24, MTOT, 0, 0, 0, 0, 1.f, 0);
    softmax_k<<<MTOT, 256>>>(ps, prh, prl, 1);
    gemm_tc<4,0,1><<<gPV, 256, GEMM_SMEM>>>(mPh, mPl, prh, prl, vth, vtl,
        nullptr, phf, nullptr, nullptr, Sn, 64, 256, En, Sn, Sn, 0, sQE, 1.f, 2);
    add_ln_k<<<MTOT, 256>>>(x, phf, ln1_g, ln1_b, x1, x1h, x1l);

    // ---- cross-attention ----
    split2_k<<<dim3(148, 2), 256>>>(wq2_w, wh + oWQ2, wl + oWQ2,
                                    wk2_w, wh + oWK2, wl + oWK2, nW, En, En);
    gemm_tc<0,1,0><<<gProj, 256, GEMM_SMEM>>>(mPh, mPl, x1h, x1l, wh + oWQ2, wl + oWQ2,
        wq2_b, nullptr, qh, ql, En, 24, 24, En, 0, 0, 0, 0, 1.f, 0);
    gemm_tc<0,1,0><<<gProj, 256, GEMM_SMEM>>>(mPh, mPl, kvh, kvl, wh + oWK2, wl + oWK2,
        wk2_b, nullptr, kh, kl, En, 24, 24, En, 0, 0, 0, 0, 1.f, 0);
    gemm_tc<3,1,0><<<gVT, 256, GEMM_SMEM>>>(mPh, mPl, wh + oWV2, wl + oWV2, kvh, kvl,
        wv2_b, nullptr, vth, vtl, En, 24, 24, MTOT, 0, 0, 0, 0, 1.f, 0);
    gemm_tc<2,0,0><<<gScore, 256, GEMM_SMEM>>>(mPh, mPl, qh, ql, kh, kl,
        nullptr, ps, nullptr, nullptr, En, 24, 24, Sn, Sn, 0, Sn, sSS, scale, 0);
    softmax_k<<<MTOT, 256>>>(ps, prh, prl, 0);
    gemm_tc<4,0,1><<<gPV, 256, GEMM_SMEM>>>(mPh, mPl, prh, prl, vth, vtl,
        nullptr, phf, nullptr, nullptr, Sn, 64, 256, En, Sn, Sn, 0, sQE, 1.f, 0);
    add_ln_k<<<MTOT, 256>>>(x1, phf, ln2_g, ln2_b, x2, x2h, x2l);

    // ---- MLP ----
    split2_k<<<dim3(592, 2), 256>>>(w1, wh + oW1, wl + oW1,
                                    w2, wh + oW2, wl + oW2, nFF, En, DFFn);
    gemm_tc<1,1,0><<<gFF1, 256, GEMM_SMEM>>>(mPh, mPl, x2h, x2l, wh + oW1, wl + oW1,
        b1, nullptr, hh, hl, En, 24, 24, DFFn, 0, 0, 0, 0, 1.f, 0);
    gemm_tc<1,0,0><<<gFF2, 256, GEMM_SMEM>>>(mPh, mPl, hh, hl, wh + oW2, wl + oW2,
        b2, pmlp, nullptr, nullptr, DFFn, 96, 96, En, 0, 0, 0, 0, 1.f, 0);
    add_ln_k<<<MTOT, 256>>>(x2, pmlp, ln3_g, ln3_b, out, nullptr, nullptr);
}

// round 16
// speedup vs baseline: 1.2175x; 1.2175x over previous
#include <cuda.h>
#include <cuda_runtime.h>
#include <cuda_bf16.h>
#include <cstdint>
#include <math.h>

// ---------------------------------------------------------------------------
// Problem constants
// ---------------------------------------------------------------------------
#define Bn   4
#define Sn   2048
#define En   768
#define DFFn 3072
#define MTOT (Bn * Sn)          // 8192
#define LNEPS 1e-5f

#if defined(__CUDA_ARCH__) && \
    (defined(__CUDA_ARCH_FEAT_SM103_ALL) || defined(__CUDA_ARCH_FEAT_SM100_ALL) || \
     defined(__CUDA_ARCH_FEAT_SM101_ALL) || \
     (defined(__CUDA_ARCH_SPECIFIC__)        && (__CUDA_ARCH_SPECIFIC__        >= 1000)) || \
     (defined(__CUDA_ARCH_FAMILY_SPECIFIC__) && (__CUDA_ARCH_FAMILY_SPECIFIC__ >= 1000)))
#define HAS_TC 1
#else
#define HAS_TC 0
#endif

typedef __nv_bfloat16 bf16;

// ---------------------------------------------------------------------------
// Scratch. bf16 operand tensors in SW64 PANEL layout: 128 rows x 32 cols per
// panel (8 KB, 64-byte rows), panel index = rowBlk*(kd/32) + kBlk.
// probs (g_ph/g_pl) and fp32 tensors stay row-major.
// ---------------------------------------------------------------------------
__device__ __align__(128) bf16  g_qh [MTOT * En],  g_ql [MTOT * En];
__device__ __align__(128) bf16  g_kh [MTOT * En],  g_kl [MTOT * En];
__device__ __align__(128) bf16  g_vth[MTOT * En],  g_vtl[MTOT * En];   // V^T panels [En, MTOT]
__device__ __align__(128) float g_s  [(size_t)Bn * Sn * Sn];           // raw scores
__device__ __align__(128) bf16  g_ph [(size_t)Bn * Sn * Sn];           // prob planes (row-major)
__device__ __align__(128) bf16  g_pl [(size_t)Bn * Sn * Sn];
__device__ __align__(128) bf16  g_hh [(size_t)MTOT * DFFn];            // MLP hidden panels
__device__ __align__(128) bf16  g_hl [(size_t)MTOT * DFFn];
__device__ __align__(128) float g_h  [MTOT * En];
__device__ __align__(128) float g_x1 [MTOT * En];
__device__ __align__(128) bf16  g_x1h[MTOT * En], g_x1l[MTOT * En];
__device__ __align__(128) float g_x2 [MTOT * En];
__device__ __align__(128) bf16  g_x2h[MTOT * En], g_x2l[MTOT * En];
__device__ __align__(128) float g_mlp[MTOT * En];
__device__ __align__(128) bf16  g_xh [MTOT * En], g_xl [MTOT * En];
__device__ __align__(128) bf16  g_kvh[MTOT * En], g_kvl[MTOT * En];
__device__ __align__(128) bf16  g_wh [6 * En * En + 2 * DFFn * En];
__device__ __align__(128) bf16  g_wl [6 * En * En + 2 * DFFn * En];

// ---------------------------------------------------------------------------
// SW64 panel addressing: panel 128 rows x 32 cols, 64-byte rows.
// Swizzle<SW64>: byte ^= (byte>>3) & 0x30.
// ---------------------------------------------------------------------------
__device__ __forceinline__ long panel_off(int row, int col, int kd) {
    long p = (long)(row >> 7) * (kd >> 5) + (col >> 5);
    uint32_t b = (uint32_t)((row & 127) * 64 + (col & 31) * 2);
    b ^= (b >> 3) & 0x30;
    return p * 8192 + b;
}

__device__ __forceinline__ uint32_t smem_u32(const void* p) {
    uint32_t a;
    asm("{ .reg .u64 t; cvta.to.shared.u64 t, %1; cvt.u32.u64 %0, t; }"
        : "=r"(a) : "l"(p));
    return a;
}

__device__ __forceinline__ void bf16_split(float x, bf16& h, bf16& l) {
    h = __float2bfloat16_rn(x);
    l = __float2bfloat16_rn(x - __bfloat162float(h));
}

__device__ __forceinline__ uint32_t pack2(bf16 a, bf16 b) {
    __nv_bfloat162 t(a, b);
    return *(uint32_t*)&t;
}

__device__ __forceinline__ float panel_read(const bf16* p, int row, int col, int kd) {
    return __bfloat162float(*(const bf16*)((const char*)p + panel_off(row, col, kd)));
}

#if HAS_TC
__device__ __forceinline__ uint32_t elect_one() {
    uint32_t pred;
    asm volatile("{\n\t.reg .pred p;\n\telect.sync _|p, 0xFFFFFFFF;\n\t"
                 "selp.b32 %0, 1, 0, p;\n\t}" : "=r"(pred));
    return pred;
}

#define MBARRIER_INIT(addr, cnt) \
    asm volatile("mbarrier.init.shared.b64 [%0], %1;" :: "r"(addr), "r"(cnt) : "memory")

#define MBARRIER_EXPECT_TX(addr, bytes) \
    asm volatile("mbarrier.arrive.expect_tx.shared.b64 _, [%0], %1;" \
                 :: "r"((uint32_t)(addr)), "r"((uint32_t)(bytes)) : "memory")

#define MBARRIER_WAIT_PARITY(mbar_addr, phase_parity) do {                          \
    uint32_t _mbar = (uint32_t)(mbar_addr);                                         \
    uint32_t _par  = (uint32_t)(phase_parity);                                      \
    uint32_t _done;                                                                 \
    asm volatile("{\n\t.reg .pred p;\n\t"                                           \
        "mbarrier.try_wait.parity.acquire.cta.shared::cta.b64 p, [%1], %2;\n\t"     \
        "selp.b32 %0, 1, 0, p;\n\t}"                                                \
        : "=r"(_done) : "r"(_mbar), "r"(_par) : "memory");                          \
    if (!_done) {                                                                   \
        asm volatile("{\n\t.reg .pred P1;\n\t"                                      \
        "WAIT_LOOP_%=:\n\t"                                                         \
        "mbarrier.try_wait.parity.acquire.cta.shared::cta.b64 P1, [%0], %1, 0x989680;\n\t" \
        "@P1 bra.uni WAIT_DONE_%=;\n\t"                                             \
        "bra.uni WAIT_LOOP_%=;\n\t"                                                 \
        "WAIT_DONE_%=:\n\t}"                                                        \
        :: "r"(_mbar), "r"(_par) : "memory");                                       \
    }                                                                               \
} while (0)

#define TCGEN05_ALLOC(smem_res, ncols) \
    asm volatile("tcgen05.alloc.cta_group::1.sync.aligned.shared::cta.b32 [%0], %1;" \
                 :: "r"((uint32_t)(smem_res)), "r"((uint32_t)(ncols)) : "memory")
#define TCGEN05_DEALLOC(tmem, ncols) \
    asm volatile("tcgen05.dealloc.cta_group::1.sync.aligned.b32 %0, %1;" \
                 :: "r"(tmem), "r"((uint32_t)(ncols)))
#define TCGEN05_RELINQUISH() \
    asm volatile("tcgen05.relinquish_alloc_permit.cta_group::1.sync.aligned;")
#define TCGEN05_COMMIT(mbar) \
    asm volatile("tcgen05.commit.cta_group::1.mbarrier::arrive::one.shared::cluster.b64 [%0];" \
                 :: "r"((uint32_t)(mbar)) : "memory")
#define TCGEN05_FENCE_AFTER() \
    asm volatile("tcgen05.fence::after_thread_sync;" ::: "memory")
#define TCGEN05_FENCE_BEFORE() \
    asm volatile("tcgen05.fence::before_thread_sync;" ::: "memory")
#define TCGEN05_WAIT_LD() \
    asm volatile("tcgen05.wait::ld.sync.aligned;" ::: "memory")

#define BULK_LOAD(dst, src, bytes, mbar) \
    asm volatile("cp.async.bulk.shared::cluster.global.mbarrier::complete_tx::bytes " \
                 "[%0], [%1], %2, [%3];" \
                 :: "r"((uint32_t)(dst)), "l"(src), "r"((uint32_t)(bytes)), \
                    "r"((uint32_t)(mbar)) : "memory")

#define TMA_LOAD_2D(smem_addr, map, cx, cy, mbar) \
    asm volatile( \
        "cp.async.bulk.tensor.2d.shared::cta.global.tile.mbarrier::complete_tx::bytes " \
        "[%0], [%1, {%2, %3}], [%4];" \
        :: "r"((uint32_t)(smem_addr)), "l"(map), "r"((int)(cx)), "r"((int)(cy)), \
           "r"((uint32_t)(mbar)) : "memory")

#define TCGEN05_LD_32X32B_X32(r, tmem_addr) \
    asm volatile( \
        "tcgen05.ld.sync.aligned.32x32b.x32.b32 " \
        "{%0, %1, %2, %3, %4, %5, %6, %7, " \
        " %8, %9, %10, %11, %12, %13, %14, %15, " \
        " %16, %17, %18, %19, %20, %21, %22, %23, " \
        " %24, %25, %26, %27, %28, %29, %30, %31}, [%32];" \
        : "=r"((r)[0]),  "=r"((r)[1]),  "=r"((r)[2]),  "=r"((r)[3]), \
          "=r"((r)[4]),  "=r"((r)[5]),  "=r"((r)[6]),  "=r"((r)[7]), \
          "=r"((r)[8]),  "=r"((r)[9]),  "=r"((r)[10]), "=r"((r)[11]), \
          "=r"((r)[12]), "=r"((r)[13]), "=r"((r)[14]), "=r"((r)[15]), \
          "=r"((r)[16]), "=r"((r)[17]), "=r"((r)[18]), "=r"((r)[19]), \
          "=r"((r)[20]), "=r"((r)[21]), "=r"((r)[22]), "=r"((r)[23]), \
          "=r"((r)[24]), "=r"((r)[25]), "=r"((r)[26]), "=r"((r)[27]), \
          "=r"((r)[28]), "=r"((r)[29]), "=r"((r)[30]), "=r"((r)[31]) \
        : "r"(tmem_addr))

// SW64 K-major smem descriptor: layout 4, version 1, SBO=32, LBO=1.
__device__ __forceinline__ uint64_t make_desc(uint32_t addr) {
    constexpr uint64_t base =
        (uint64_t(4)  << 61) | (uint64_t(1) << 46) |
        (uint64_t(32) << 32) | (uint64_t(1) << 16);
    return base | ((uint64_t)(addr >> 4) & 0x3FFF);
}

__device__ __forceinline__ void mma_bf16(uint32_t d_tmem, uint64_t da, uint64_t db,
                                         uint32_t idesc, uint32_t acc) {
    asm volatile(
        "{\n\t.reg .pred p;\n\tsetp.ne.u32 p, %4, 0;\n\t"
        "tcgen05.mma.cta_group::1.kind::f16 [%0], %1, %2, %3, {%5, %5, %5, %5}, p;\n\t}"
        :: "r"(d_tmem), "l"(da), "l"(db), "r"(idesc), "r"(acc), "r"(0u)
        : "memory");
}
#endif  // HAS_TC

// ---------------------------------------------------------------------------
// GEMM (NT): C = A * B^T, bf16 (hi,lo) planes, 3-pass. Tiles BM=128, BN=256,
// BK=32. 4-stage mbarrier ring (stage 48KB): producer keeps up to 3 chunks in
// flight. Stage s = c & 3; completion index c>>2 drives parities.
//   EPI 0:+bias[n] 1:relu(+bias[n]) 2:*scale 3:+bias[m] 4:none
//   OUT 0: fp32 row-major C   1: bf16 panel planes (Ch, Cl)
//   causal 0:none 1:skip upper tiles 2:K-limit (causal PV)
//   LOADA 1: A via 2D TMA SW64 (row-major probs); else A panels via bulk copy.
// ---------------------------------------------------------------------------
static constexpr int SM_TILE0  = 1024;
static constexpr int SM_A_HI   = 0;          // 128x32 bf16 = 8 KB
static constexpr int SM_A_LO   = 8192;
static constexpr int SM_B_HI   = 16384;      // 256x32 bf16 = 16 KB (2 panels)
static constexpr int SM_B_LO   = 32768;
static constexpr int SM_STAGE  = 49152;
static constexpr int GEMM_SMEM = SM_TILE0 + 4 * SM_STAGE;   // 197632 B
static constexpr uint32_t IDESC_BF16 =
    (1u << 4) | (1u << 7) | (1u << 10) | ((256u / 8u) << 17) | ((128u / 16u) << 24);

// Control smem: 0 = tmem ptr, empty[s] = 8+s*8 (s<4), full[s] = 40+s*8.
template<int EPI, int OUT, int LOADA>
__global__ void __launch_bounds__(256, 1)
gemm_tc(const __grid_constant__ CUtensorMap tmAh,
        const __grid_constant__ CUtensorMap tmAl,
        const bf16* __restrict__ Aph, const bf16* __restrict__ Apl,
        const bf16* __restrict__ Bph, const bf16* __restrict__ Bpl,
        const float* __restrict__ bias,
        float* __restrict__ C, bf16* __restrict__ Ch, bf16* __restrict__ Cl,
        int K, int KAB, int KBB, int ldc,
        int aYoff, int bXoff, int bYoff, long sC, float scale, int causal)
{
    extern __shared__ __align__(1024) char smem[];
    const int tid = threadIdx.x;

    const int rm = blockIdx.y * 128;
    const int cn = blockIdx.x * 256;
    if (causal == 1 && cn > rm + 127) return;

    if (OUT == 0) C += (long)blockIdx.z * sC;

    int Keff = K;
    if (causal == 2) Keff = min(K, rm + 128);

#if HAS_TC
    const uint32_t smem_base = smem_u32(smem);
    const int wid = tid >> 5;

    if (tid == 0) {
#pragma unroll
        for (int s = 0; s < 4; s++) {
            MBARRIER_INIT(smem_base + 8 + s * 8, 1);    // empty[s]
            MBARRIER_INIT(smem_base + 40 + s * 8, 1);   // full[s]
        }
    }
    if (wid == 5) TCGEN05_ALLOC(smem_base + 0, 256);
    __syncthreads();

    uint32_t tmem;
    asm volatile("ld.shared.b32 %0, [%1];" : "=r"(tmem) : "r"(smem_base));

    const int NC = Keff >> 5;                 // BK = 32
    const int ay  = blockIdx.z * aYoff + rm;  // TMA row (LOADA=1)
    const long aP = ((long)((blockIdx.z * aYoff + rm) >> 7)) * KAB;
    const long bP0 = ((long)((blockIdx.z * bYoff + cn) >> 7)) * KBB;
    const long bP1 = bP0 + KBB;
    const int  kB0 = (blockIdx.z * bXoff) >> 5;

    if (wid == 4 && elect_one()) {
        // ---------------- producer (single thread) ----------------
        for (int c = 0; c < NC; c++) {
            const int s = c & 3;
            if (c >= 4)  // stage s still owned by MMA of chunk c-4
                MBARRIER_WAIT_PARITY(smem_base + 8 + s * 8, ((c >> 2) + 1) & 1);
            const uint32_t fullb = smem_base + 40 + s * 8;
            MBARRIER_EXPECT_TX(fullb, (uint32_t)SM_STAGE);
            const uint32_t tn = smem_base + SM_TILE0 + s * SM_STAGE;
            if (LOADA == 1) {
                const int kx = c << 5;
                TMA_LOAD_2D(tn + SM_A_HI, &tmAh, kx, ay, fullb);
                TMA_LOAD_2D(tn + SM_A_LO, &tmAl, kx, ay, fullb);
            } else {
                const long pa = (aP + c) * 8192;
                BULK_LOAD(tn + SM_A_HI, (const char*)Aph + pa, 8192, fullb);
                BULK_LOAD(tn + SM_A_LO, (const char*)Apl + pa, 8192, fullb);
            }
            const long pb0 = (bP0 + kB0 + c) * 8192;
            const long pb1 = (bP1 + kB0 + c) * 8192;
            BULK_LOAD(tn + SM_B_HI,        (const char*)Bph + pb0, 8192, fullb);
            BULK_LOAD(tn + SM_B_HI + 8192, (const char*)Bph + pb1, 8192, fullb);
            BULK_LOAD(tn + SM_B_LO,        (const char*)Bpl + pb0, 8192, fullb);
            BULK_LOAD(tn + SM_B_LO + 8192, (const char*)Bpl + pb1, 8192, fullb);
        }
    } else if (wid == 5 && elect_one()) {
        // ---------------- MMA consumer (single thread) ----------------
        for (int c = 0; c < NC; c++) {
            const int s = c & 3;
            MBARRIER_WAIT_PARITY(smem_base + 40 + s * 8, (c >> 2) & 1);
            const uint32_t tb = smem_base + SM_TILE0 + s * SM_STAGE;
            const uint64_t dah = make_desc(tb + SM_A_HI);
            const uint64_t dal = make_desc(tb + SM_A_LO);
            const uint64_t dbh = make_desc(tb + SM_B_HI);
            const uint64_t dbl = make_desc(tb + SM_B_LO);
#pragma unroll
            for (int st = 0; st < 2; st++)       // hi*hi  (K=16 per step)
                mma_bf16(tmem, dah + st * 2, dbh + st * 2, IDESC_BF16,
                         (c == 0 && st == 0) ? 0u : 1u);
#pragma unroll
            for (int st = 0; st < 2; st++)       // hi*lo
                mma_bf16(tmem, dah + st * 2, dbl + st * 2, IDESC_BF16, 1u);
#pragma unroll
            for (int st = 0; st < 2; st++)       // lo*hi
                mma_bf16(tmem, dal + st * 2, dbh + st * 2, IDESC_BF16, 1u);
            TCGEN05_COMMIT(smem_base + 8 + s * 8);
        }
    }
    // Gate idle/epilogue warps so the tile-final parity wait is unambiguous.
    __syncthreads();

    const int cL = NC - 1;
    MBARRIER_WAIT_PARITY(smem_base + 8 + (cL & 3) * 8, (cL >> 2) & 1);
    TCGEN05_FENCE_AFTER();

    if (wid < 4) {
        const int lane = tid & 31;
        const int m = rm + wid * 32 + lane;
        const float biasm = (EPI == 3) ? bias[m] : 0.f;
#pragma unroll
        for (int seg = 0; seg < 8; seg++) {
            uint32_t r[32];
            TCGEN05_LD_32X32B_X32(r, tmem + seg * 32);
            TCGEN05_WAIT_LD();
#pragma unroll
            for (int j = 0; j < 32; j += 4) {
                float v[4];
#pragma unroll
                for (int tt = 0; tt < 4; tt++) {
                    const int n = cn + seg * 32 + j + tt;
                    float x = __uint_as_float(r[j + tt]);
                    if (EPI == 0)      x += bias[n];
                    else if (EPI == 1) x = fmaxf(x + bias[n], 0.f);
                    else if (EPI == 2) x *= scale;
                    else if (EPI == 3) x += biasm;
                    v[tt] = x;
                }
                if (OUT == 0) {
                    *(float4*)(C + (long)m * ldc + cn + seg * 32 + j) =
                        make_float4(v[0], v[1], v[2], v[3]);
                } else {
                    bf16 h0, l0, h1, l1, h2, l2, h3, l3;
                    bf16_split(v[0], h0, l0); bf16_split(v[1], h1, l1);
                    bf16_split(v[2], h2, l2); bf16_split(v[3], h3, l3);
                    const long off = panel_off(m, cn + seg * 32 + j, ldc);
                    uint2 uh, ul;
                    uh.x = pack2(h0, h1); uh.y = pack2(h2, h3);
                    ul.x = pack2(l0, l1); ul.y = pack2(l2, l3);
                    *(uint2*)((char*)Ch + off) = uh;
                    *(uint2*)((char*)Cl + off) = ul;
                }
            }
        }
        TCGEN05_FENCE_BEFORE();
    }
    __syncthreads();
    if (wid == 5) {
        TCGEN05_RELINQUISH();
        TCGEN05_DEALLOC(tmem, 256);
    }
#else
    // --------------------- SIMT fp32 fallback path -------------------------
    constexpr int BK = 16;
    float (*As)[132] = (float (*)[132])(smem);
    float (*Bs)[132] = (float (*)[132])(smem + BK * 132 * sizeof(float));
    const int tx = tid & 15, ty = tid >> 4;
    const int lda = KAB * 32, ldbK = KBB * 32;

    for (int half = 0; half < 2; half++) {
        const int cnh = cn + half * 128;
        float acc[8][8];
#pragma unroll
        for (int i = 0; i < 8; i++)
#pragma unroll
            for (int j = 0; j < 8; j++) acc[i][j] = 0.f;

        for (int k0 = 0; k0 < Keff; k0 += BK) {
#pragma unroll
            for (int i = 0; i < 2; i++) {
                const int q = i * 256 + tid;
                const int row = q >> 1, kc = (q & 1) * 8;
#pragma unroll
                for (int u = 0; u < 8; u++) {
                    const int k = k0 + kc + u;
                    float av;
                    if (LOADA == 1) {
                        const long ai = (long)(blockIdx.z * aYoff + rm + row) * lda + k;
                        av = __bfloat162float(Aph[ai]) + __bfloat162float(Apl[ai]);
                    } else {
                        const int gr = blockIdx.z * aYoff + rm + row;
                        av = panel_read(Aph, gr, k, lda) + panel_read(Apl, gr, k, lda);
                    }
                    const int gbr = blockIdx.z * bYoff + cnh + row;
                    const int gbk = blockIdx.z * bXoff + k;
                    As[kc + u][row] = av;
                    Bs[kc + u][row] = panel_read(Bph, gbr, gbk, ldbK) +
                                      panel_read(Bpl, gbr, gbk, ldbK);
                }
            }
            __syncthreads();
#pragma unroll
            for (int kk = 0; kk < BK; kk++) {
                float a[8], b[8];
#pragma unroll
                for (int i = 0; i < 8; i++) a[i] = As[kk][ty * 8 + i];
#pragma unroll
                for (int j = 0; j < 8; j++) b[j] = Bs[kk][tx * 8 + j];
#pragma unroll
                for (int i = 0; i < 8; i++)
#pragma unroll
                    for (int j = 0; j < 8; j++) acc[i][j] += a[i] * b[j];
            }
            __syncthreads();
        }

#pragma unroll
        for (int i = 0; i < 8; i++) {
            const int m = rm + ty * 8 + i;
            const float biasm = (EPI == 3) ? bias[m] : 0.f;
#pragma unroll
            for (int j = 0; j < 8; j++) {
                const int n = cnh + tx * 8 + j;
                float x = acc[i][j];
                if (EPI == 0)      x += bias[n];
                else if (EPI == 1) x = fmaxf(x + bias[n], 0.f);
                else if (EPI == 2) x *= scale;
                else if (EPI == 3) x += biasm;
                if (OUT == 0) C[(long)m * ldc + n] = x;
                else {
                    bf16 hh, ll;
                    bf16_split(x, hh, ll);
                    const long off = panel_off(m, n, ldc);
                    *(bf16*)((char*)Ch + off) = hh;
                    *(bf16*)((char*)Cl + off) = ll;
                }
            }
        }
        __syncthreads();
    }
#endif
}

// ---------------------------------------------------------------------------
// Elementwise bf16 Dekker split -> SW64 PANEL layout. Two tensors per launch.
// ---------------------------------------------------------------------------
__device__ __forceinline__ void split_body(const float* __restrict__ src,
                                           bf16* __restrict__ hi,
                                           bf16* __restrict__ lo, long n4, int kd)
{
    for (long i = blockIdx.x * 256L + threadIdx.x; i < n4; i += (long)gridDim.x * 256) {
        const float4 f = *(const float4*)(src + i * 4);
        bf16 h0, l0, h1, l1, h2, l2, h3, l3;
        bf16_split(f.x, h0, l0); bf16_split(f.y, h1, l1);
        bf16_split(f.z, h2, l2); bf16_split(f.w, h3, l3);
        const long e0 = i * 4;
        const int row = (int)(e0 / kd);
        const int col = (int)(e0 - (long)row * kd);
        const long off = panel_off(row, col, kd);
        uint2 uh, ul;
        uh.x = pack2(h0, h1); uh.y = pack2(h2, h3);
        ul.x = pack2(l0, l1); ul.y = pack2(l2, l3);
        *(uint2*)((char*)hi + off) = uh;
        *(uint2*)((char*)lo + off) = ul;
    }
}

__global__ void __launch_bounds__(256)
split2_k(const float* __restrict__ s0, bf16* __restrict__ h0, bf16* __restrict__ l0,
         const float* __restrict__ s1, bf16* __restrict__ h1, bf16* __restrict__ l1,
         long n4, int kd0, int kd1)
{
    if (blockIdx.y == 0) split_body(s0, h0, l0, n4, kd0);
    else                 split_body(s1, h1, l1, n4, kd1);
}

// ---------------------------------------------------------------------------
// Row softmax over fp32 scores -> bf16 (hi, lo) prob planes (row-major).
// ---------------------------------------------------------------------------
__global__ void __launch_bounds__(256)
softmax_k(const float* __restrict__ S, bf16* __restrict__ Ph,
          bf16* __restrict__ Pl, int causal)
{
    const int row = blockIdx.x;
    const int b = row >> 11;
    const int i = row & 2047;
    const float* p = S + (long)b * Sn * Sn + (long)i * Sn;
    bf16* ph = Ph + (long)b * Sn * Sn + (long)i * Sn;
    bf16* pl = Pl + (long)b * Sn * Sn + (long)i * Sn;
    const int L = causal ? (i + 1) : Sn;
    const int FILL = causal ? (((i >> 7) + 1) << 7) : Sn;
    const int tid = threadIdx.x;
    __shared__ float sh[8];

    float m = -3.4e38f;
    for (int j = tid; j < L; j += 256) m = fmaxf(m, p[j]);
#pragma unroll
    for (int o = 16; o > 0; o >>= 1) m = fmaxf(m, __shfl_xor_sync(~0u, m, o));
    if ((tid & 31) == 0) sh[tid >> 5] = m;
    __syncthreads();
    m = sh[0];
#pragma unroll
    for (int w = 1; w < 8; w++) m = fmaxf(m, sh[w]);

    float s = 0.f;
    for (int j = tid; j < L; j += 256) s += __expf(p[j] - m);
#pragma unroll
    for (int o = 16; o > 0; o >>= 1) s += __shfl_xor_sync(~0u, s, o);
    __syncthreads();
    if ((tid & 31) == 0) sh[tid >> 5] = s;
    __syncthreads();
    s = 0.f;
#pragma unroll
    for (int w = 0; w < 8; w++) s += sh[w];
    const float inv = 1.f / s;

    for (int j = tid; j < L; j += 256) {
        const float v = __expf(p[j] - m) * inv;
        bf16 hh, ll;
        bf16_split(v, hh, ll);
        ph[j] = hh;
        pl[j] = ll;
    }
    const bf16 z = __float2bfloat16(0.f);
    for (int j = L + tid; j < FILL; j += 256) { ph[j] = z; pl[j] = z; }
}

// ---------------------------------------------------------------------------
// y = LayerNorm(x + h) * g + b; optional SW64-panel bf16 splits (yh, yl).
// ---------------------------------------------------------------------------
__global__ void __launch_bounds__(256)
add_ln_k(const float* __restrict__ x, const float* __restrict__ h,
         const float* __restrict__ g, const float* __restrict__ bt,
         float* __restrict__ y, bf16* __restrict__ yh, bf16* __restrict__ yl)
{
    const long row = blockIdx.x;
    const float* xr = x + row * En;
    const float* hr = h + row * En;
    const int tid = threadIdx.x;

    float v[3];
    float s = 0.f, s2 = 0.f;
#pragma unroll
    for (int t = 0; t < 3; t++) {
        const int c = tid + t * 256;
        const float u = xr[c] + hr[c];
        v[t] = u;
        s += u;
        s2 += u * u;
    }
    __shared__ float shA[8], shB[8];
#pragma unroll
    for (int o = 16; o > 0; o >>= 1) {
        s  += __shfl_xor_sync(~0u, s,  o);
        s2 += __shfl_xor_sync(~0u, s2, o);
    }
    if ((tid & 31) == 0) { shA[tid >> 5] = s; shB[tid >> 5] = s2; }
    __syncthreads();
    s = 0.f; s2 = 0.f;
#pragma unroll
    for (int w = 0; w < 8; w++) { s += shA[w]; s2 += shB[w]; }

    const float mu   = s * (1.f / En);
    const float var  = s2 * (1.f / En) - mu * mu;
    const float rstd = rsqrtf(var + LNEPS);
#pragma unroll
    for (int t = 0; t < 3; t++) {
        const int c = tid + t * 256;
        const float o = (v[t] - mu) * rstd * g[c] + bt[c];
        y[row * En + c] = o;
        if (yh) {
            bf16 hh, ll;
            bf16_split(o, hh, ll);
            const long off = panel_off((int)row, c, En);
            *(bf16*)((char*)yh + off) = hh;
            *(bf16*)((char*)yl + off) = ll;
        }
    }
}

// ---------------------------------------------------------------------------
// Host: tensor-map encoding (probs only; SW64, box {32, boxRows}).
// ---------------------------------------------------------------------------
typedef CUresult (*PFN_tmEncode)(
    CUtensorMap*, CUtensorMapDataType, cuuint32_t, void*,
    const cuuint64_t*, const cuuint64_t*, const cuuint32_t*, const cuuint32_t*,
    CUtensorMapInterleave, CUtensorMapSwizzle, CUtensorMapL2promotion,
    CUtensorMapFloatOOBfill);

static PFN_tmEncode tm_encoder() {
    static PFN_tmEncode fn = nullptr;
    if (!fn) {
        void* p = nullptr;
        cudaDriverEntryPointQueryResult st;
#if CUDART_VERSION >= 12050
        cudaGetDriverEntryPointByVersion("cuTensorMapEncodeTiled", &p, 12000,
                                         cudaEnableDefault, &st);
#else
        cudaGetDriverEntryPoint("cuTensorMapEncodeTiled", &p,
                                cudaEnableDefault, &st);
#endif
        fn = (PFN_tmEncode)p;
    }
    return fn;
}

static CUtensorMap make_map(const void* base, long rowElems, long nRows, int boxRows)
{
    CUtensorMap m;
    cuuint64_t dims[2]    = {(cuuint64_t)rowElems, (cuuint64_t)nRows};
    cuuint64_t strides[1] = {(cuuint64_t)rowElems * 2};
    cuuint32_t box[2]     = {32u, (cuuint32_t)boxRows};
    cuuint32_t es[2]      = {1u, 1u};
    tm_encoder()(&m, CU_TENSOR_MAP_DATA_TYPE_BFLOAT16, 2, (void*)base,
                 dims, strides, box, es,
                 CU_TENSOR_MAP_INTERLEAVE_NONE, CU_TENSOR_MAP_SWIZZLE_64B,
                 CU_TENSOR_MAP_L2_PROMOTION_L2_128B,
                 CU_TENSOR_MAP_FLOAT_OOB_FILL_NONE);
    return m;
}

// ---------------------------------------------------------------------------
// Host launcher
// ---------------------------------------------------------------------------
extern "C" void kernel_launch(void* const* d_in, const int* in_sizes, int n_in,
                              void* d_out, int out_size)
{
    const float* x     = (const float*)d_in[0];
    const float* kv    = (const float*)d_in[1];
    const float* wq_w  = (const float*)d_in[2];
    const float* wq_b  = (const float*)d_in[3];
    const float* wk_w  = (const float*)d_in[4];
    const float* wk_b  = (const float*)d_in[5];
    const float* wv_w  = (const float*)d_in[6];
    const float* wv_b  = (const float*)d_in[7];
    const float* ln1_g = (const float*)d_in[8];
    const float* ln1_b = (const float*)d_in[9];
    const float* wq2_w = (const float*)d_in[10];
    const float* wq2_b = (const float*)d_in[11];
    const float* wk2_w = (const float*)d_in[12];
    const float* wk2_b = (const float*)d_in[13];
    const float* wv2_w = (const float*)d_in[14];
    const float* wv2_b = (const float*)d_in[15];
    const float* ln2_g = (const float*)d_in[16];
    const float* ln2_b = (const float*)d_in[17];
    const float* w1    = (const float*)d_in[18];
    const float* b1    = (const float*)d_in[19];
    const float* w2    = (const float*)d_in[20];
    const float* b2    = (const float*)d_in[21];
    const float* ln3_g = (const float*)d_in[22];
    const float* ln3_b = (const float*)d_in[23];
    float* out = (float*)d_out;

    bf16 *qh, *ql, *kh, *kl, *vth, *vtl, *prh, *prl, *hh, *hl;
    bf16 *x1h, *x1l, *x2h, *x2l, *xh, *xl, *kvh, *kvl, *wh, *wl;
    float *ps, *phf, *x1, *x2, *pmlp;
    cudaGetSymbolAddress((void**)&qh,  g_qh);   cudaGetSymbolAddress((void**)&ql,  g_ql);
    cudaGetSymbolAddress((void**)&kh,  g_kh);   cudaGetSymbolAddress((void**)&kl,  g_kl);
    cudaGetSymbolAddress((void**)&vth, g_vth);  cudaGetSymbolAddress((void**)&vtl, g_vtl);
    cudaGetSymbolAddress((void**)&prh, g_ph);   cudaGetSymbolAddress((void**)&prl, g_pl);
    cudaGetSymbolAddress((void**)&hh,  g_hh);   cudaGetSymbolAddress((void**)&hl,  g_hl);
    cudaGetSymbolAddress((void**)&x1h, g_x1h);  cudaGetSymbolAddress((void**)&x1l, g_x1l);
    cudaGetSymbolAddress((void**)&x2h, g_x2h);  cudaGetSymbolAddress((void**)&x2l, g_x2l);
    cudaGetSymbolAddress((void**)&xh,  g_xh);   cudaGetSymbolAddress((void**)&xl,  g_xl);
    cudaGetSymbolAddress((void**)&kvh, g_kvh);  cudaGetSymbolAddress((void**)&kvl, g_kvl);
    cudaGetSymbolAddress((void**)&wh,  g_wh);   cudaGetSymbolAddress((void**)&wl,  g_wl);
    cudaGetSymbolAddress((void**)&ps,  g_s);
    cudaGetSymbolAddress((void**)&phf, g_h);
    cudaGetSymbolAddress((void**)&x1,  g_x1);
    cudaGetSymbolAddress((void**)&x2,  g_x2);
    cudaGetSymbolAddress((void**)&pmlp, g_mlp);

    const long oWQ = 0, oWK = oWQ + (long)En * En, oWV = oWK + (long)En * En;
    const long oWQ2 = oWV + (long)En * En, oWK2 = oWQ2 + (long)En * En;
    const long oWV2 = oWK2 + (long)En * En;
    const long oW1 = oWV2 + (long)En * En, oW2 = oW1 + (long)DFFn * En;

    cudaFuncSetAttribute(gemm_tc<0,1,0>, cudaFuncAttributeMaxDynamicSharedMemorySize, GEMM_SMEM);
    cudaFuncSetAttribute(gemm_tc<3,1,0>, cudaFuncAttributeMaxDynamicSharedMemorySize, GEMM_SMEM);
    cudaFuncSetAttribute(gemm_tc<2,0,0>, cudaFuncAttributeMaxDynamicSharedMemorySize, GEMM_SMEM);
    cudaFuncSetAttribute(gemm_tc<4,0,1>, cudaFuncAttributeMaxDynamicSharedMemorySize, GEMM_SMEM);
    cudaFuncSetAttribute(gemm_tc<1,1,0>, cudaFuncAttributeMaxDynamicSharedMemorySize, GEMM_SMEM);
    cudaFuncSetAttribute(gemm_tc<1,0,0>, cudaFuncAttributeMaxDynamicSharedMemorySize, GEMM_SMEM);

    const float scale = 0.03608439182435161f;  // 1/sqrt(768)
    const long sSS = (long)Sn * Sn;
    const long sQE = (long)Sn * En;

    const dim3 gProj(En / 256, MTOT / 128, 1);
    const dim3 gVT(MTOT / 256, En / 128, 1);
    const dim3 gScore(Sn / 256, Sn / 128, Bn);
    const dim3 gPV(En / 256, Sn / 128, Bn);
    const dim3 gFF1(DFFn / 256, MTOT / 128, 1);
    const dim3 gFF2(En / 256, MTOT / 128, 1);

    const long nXY = (long)MTOT * En / 4;
    const long nW  = (long)En * En / 4;
    const long nFF = (long)DFFn * En / 4;

    CUtensorMap mPh = make_map(prh, Sn, MTOT, 128);
    CUtensorMap mPl = make_map(prl, Sn, MTOT, 128);

    // KAB/KBB = panels per 128-row block = kd/32.
    // Launch order keeps the causal score GEMM at index 5 (ncu -s 5 -c 1).
    split2_k<<<dim3(296, 2), 256>>>(x, xh, xl, kv, kvh, kvl, nXY, En, En);
    split2_k<<<dim3(148, 2), 256>>>(wq_w, wh + oWQ, wl + oWQ,
                                    wk_w, wh + oWK, wl + oWK, nW, En, En);
    gemm_tc<0,1,0><<<gProj, 256, GEMM_SMEM>>>(mPh, mPl, xh, xl, wh + oWQ, wl + oWQ,
        wq_b, nullptr, qh, ql, En, 24, 24, En, 0, 0, 0, 0, 1.f, 0);
    gemm_tc<0,1,0><<<gProj, 256, GEMM_SMEM>>>(mPh, mPl, xh, xl, wh + oWK, wl + oWK,
        wk_b, nullptr, kh, kl, En, 24, 24, En, 0, 0, 0, 0, 1.f, 0);
    split2_k<<<dim3(148, 2), 256>>>(wv_w,  wh + oWV,  wl + oWV,
                                    wv2_w, wh + oWV2, wl + oWV2, nW, En, En);
    // 5: causal score GEMM  <-- profiled launch
    gemm_tc<2,0,0><<<gScore, 256, GEMM_SMEM>>>(mPh, mPl, qh, ql, kh, kl,
        nullptr, ps, nullptr, nullptr, En, 24, 24, Sn, Sn, 0, Sn, sSS, scale, 1);
    gemm_tc<3,1,0><<<gVT, 256, GEMM_SMEM>>>(mPh, mPl, wh + oWV, wl + oWV, xh, xl,
        wv_b, nullptr, vth, vtl, En, 24, 24, MTOT, 0, 0, 0, 0, 1.f, 0);
    softmax_k<<<MTOT, 256>>>(ps, prh, prl, 1);
    gemm_tc<4,0,1><<<gPV, 256, GEMM_SMEM>>>(mPh, mPl, prh, prl, vth, vtl,
        nullptr, phf, nullptr, nullptr, Sn, 64, 256, En, Sn, Sn, 0, sQE, 1.f, 2);
    add_ln_k<<<MTOT, 256>>>(x, phf, ln1_g, ln1_b, x1, x1h, x1l);

    // ---- cross-attention ----
    split2_k<<<dim3(148, 2), 256>>>(wq2_w, wh + oWQ2, wl + oWQ2,
                                    wk2_w, wh + oWK2, wl + oWK2, nW, En, En);
    gemm_tc<0,1,0><<<gProj, 256, GEMM_SMEM>>>(mPh, mPl, x1h, x1l, wh + oWQ2, wl + oWQ2,
        wq2_b, nullptr, qh, ql, En, 24, 24, En, 0, 0, 0, 0, 1.f, 0);
    gemm_tc<0,1,0><<<gProj, 256, GEMM_SMEM>>>(mPh, mPl, kvh, kvl, wh + oWK2, wl + oWK2,
        wk2_b, nullptr, kh, kl, En, 24, 24, En, 0, 0, 0, 0, 1.f, 0);
    gemm_tc<3,1,0><<<gVT, 256, GEMM_SMEM>>>(mPh, mPl, wh + oWV2, wl + oWV2, kvh, kvl,
        wv2_b, nullptr, vth, vtl, En, 24, 24, MTOT, 0, 0, 0, 0, 1.f, 0);
    gemm_tc<2,0,0><<<gScore, 256, GEMM_SMEM>>>(mPh, mPl, qh, ql, kh, kl,
        nullptr, ps, nullptr, nullptr, En, 24, 24, Sn, Sn, 0, Sn, sSS, scale, 0);
    softmax_k<<<MTOT, 256>>>(ps, prh, prl, 0);
    gemm_tc<4,0,1><<<gPV, 256, GEMM_SMEM>>>(mPh, mPl, prh, prl, vth, vtl,
        nullptr, phf, nullptr, nullptr, Sn, 64, 256, En, Sn, Sn, 0, sQE, 1.f, 0);
    add_ln_k<<<MTOT, 256>>>(x1, phf, ln2_g, ln2_b, x2, x2h, x2l);

    // ---- MLP ----
    split2_k<<<dim3(592, 2), 256>>>(w1, wh + oW1, wl + oW1,
                                    w2, wh + oW2, wl + oW2, nFF, En, DFFn);
    gemm_tc<1,1,0><<<gFF1, 256, GEMM_SMEM>>>(mPh, mPl, x2h, x2l, wh + oW1, wl + oW1,
        b1, nullptr, hh, hl, En, 24, 24, DFFn, 0, 0, 0, 0, 1.f, 0);
    gemm_tc<1,0,0><<<gFF2, 256, GEMM_SMEM>>>(mPh, mPl, hh, hl, wh + oW2, wl + oW2,
        b2, pmlp, nullptr, nullptr, DFFn, 96, 96, En, 0, 0, 0, 0, 1.f, 0);
    add_ln_k<<<MTOT, 256>>>(x2, pmlp, ln3_g, ln3_b, out, nullptr, nullptr);
}

// round 17
// speedup vs baseline: 1.2942x; 1.0630x over previous
#include <cuda.h>
#include <cuda_runtime.h>
#include <cuda_bf16.h>
#include <cstdint>
#include <math.h>

// ---------------------------------------------------------------------------
// Problem constants
// ---------------------------------------------------------------------------
#define Bn   4
#define Sn   2048
#define En   768
#define DFFn 3072
#define MTOT (Bn * Sn)          // 8192
#define LNEPS 1e-5f

#if defined(__CUDA_ARCH__) && \
    (defined(__CUDA_ARCH_FEAT_SM103_ALL) || defined(__CUDA_ARCH_FEAT_SM100_ALL) || \
     defined(__CUDA_ARCH_FEAT_SM101_ALL) || \
     (defined(__CUDA_ARCH_SPECIFIC__)        && (__CUDA_ARCH_SPECIFIC__        >= 1000)) || \
     (defined(__CUDA_ARCH_FAMILY_SPECIFIC__) && (__CUDA_ARCH_FAMILY_SPECIFIC__ >= 1000)))
#define HAS_TC 1
#else
#define HAS_TC 0
#endif

typedef __nv_bfloat16 bf16;

// ---------------------------------------------------------------------------
// Scratch. bf16 operand tensors in SW64 PANEL layout: 128 rows x 32 cols per
// panel (8 KB, 64-byte rows), panel index = rowBlk*(kd/32) + kBlk.
// probs (g_ph/g_pl) and fp32 tensors stay row-major.
// ---------------------------------------------------------------------------
__device__ __align__(128) bf16  g_qh [MTOT * En],  g_ql [MTOT * En];
__device__ __align__(128) bf16  g_kh [MTOT * En],  g_kl [MTOT * En];
__device__ __align__(128) bf16  g_k2h[MTOT * En],  g_k2l[MTOT * En];   // cross K
__device__ __align__(128) bf16  g_vth[MTOT * En],  g_vtl[MTOT * En];   // V^T panels
__device__ __align__(128) bf16  g_vt2h[MTOT * En], g_vt2l[MTOT * En];  // cross V^T
__device__ __align__(128) float g_s  [(size_t)Bn * Sn * Sn];           // raw scores
__device__ __align__(128) bf16  g_ph [(size_t)Bn * Sn * Sn];           // prob planes
__device__ __align__(128) bf16  g_pl [(size_t)Bn * Sn * Sn];
__device__ __align__(128) bf16  g_hh [(size_t)MTOT * DFFn];            // MLP hidden
__device__ __align__(128) bf16  g_hl [(size_t)MTOT * DFFn];
__device__ __align__(128) float g_h  [MTOT * En];
__device__ __align__(128) float g_x1 [MTOT * En];
__device__ __align__(128) bf16  g_x1h[MTOT * En], g_x1l[MTOT * En];
__device__ __align__(128) float g_x2 [MTOT * En];
__device__ __align__(128) bf16  g_x2h[MTOT * En], g_x2l[MTOT * En];
__device__ __align__(128) float g_mlp[MTOT * En];
__device__ __align__(128) bf16  g_xh [MTOT * En], g_xl [MTOT * En];
__device__ __align__(128) bf16  g_kvh[MTOT * En], g_kvl[MTOT * En];
__device__ __align__(128) bf16  g_wh [6 * En * En + 2 * DFFn * En];
__device__ __align__(128) bf16  g_wl [6 * En * En + 2 * DFFn * En];

// Pointer sets for launch-fused GEMMs (blockIdx.z selects entry).
struct MArgs {
    const bf16*  Aph[3];
    const bf16*  Apl[3];
    const bf16*  Bph[3];
    const bf16*  Bpl[3];
    const float* bias[3];
    bf16*        Ch[3];
    bf16*        Cl[3];
};

// Fused split launch: blockIdx.y selects tensor.
struct SArgs {
    const float* src[10];
    bf16*        hi[10];
    bf16*        lo[10];
    long         n4[10];
    int          kd[10];
};

// ---------------------------------------------------------------------------
// SW64 panel addressing: panel 128 rows x 32 cols, 64-byte rows.
// Swizzle<SW64>: byte ^= (byte>>3) & 0x30.
// ---------------------------------------------------------------------------
__device__ __forceinline__ long panel_off(int row, int col, int kd) {
    long p = (long)(row >> 7) * (kd >> 5) + (col >> 5);
    uint32_t b = (uint32_t)((row & 127) * 64 + (col & 31) * 2);
    b ^= (b >> 3) & 0x30;
    return p * 8192 + b;
}

__device__ __forceinline__ uint32_t smem_u32(const void* p) {
    uint32_t a;
    asm("{ .reg .u64 t; cvta.to.shared.u64 t, %1; cvt.u32.u64 %0, t; }"
        : "=r"(a) : "l"(p));
    return a;
}

__device__ __forceinline__ void bf16_split(float x, bf16& h, bf16& l) {
    h = __float2bfloat16_rn(x);
    l = __float2bfloat16_rn(x - __bfloat162float(h));
}

__device__ __forceinline__ uint32_t pack2(bf16 a, bf16 b) {
    __nv_bfloat162 t(a, b);
    return *(uint32_t*)&t;
}

__device__ __forceinline__ float panel_read(const bf16* p, int row, int col, int kd) {
    return __bfloat162float(*(const bf16*)((const char*)p + panel_off(row, col, kd)));
}

#if HAS_TC
__device__ __forceinline__ uint32_t elect_one() {
    uint32_t pred;
    asm volatile("{\n\t.reg .pred p;\n\telect.sync _|p, 0xFFFFFFFF;\n\t"
                 "selp.b32 %0, 1, 0, p;\n\t}" : "=r"(pred));
    return pred;
}

#define MBARRIER_INIT(addr, cnt) \
    asm volatile("mbarrier.init.shared.b64 [%0], %1;" :: "r"(addr), "r"(cnt) : "memory")

#define MBARRIER_EXPECT_TX(addr, bytes) \
    asm volatile("mbarrier.arrive.expect_tx.shared.b64 _, [%0], %1;" \
                 :: "r"((uint32_t)(addr)), "r"((uint32_t)(bytes)) : "memory")

#define MBARRIER_WAIT_PARITY(mbar_addr, phase_parity) do {                          \
    uint32_t _mbar = (uint32_t)(mbar_addr);                                         \
    uint32_t _par  = (uint32_t)(phase_parity);                                      \
    uint32_t _done;                                                                 \
    asm volatile("{\n\t.reg .pred p;\n\t"                                           \
        "mbarrier.try_wait.parity.acquire.cta.shared::cta.b64 p, [%1], %2;\n\t"     \
        "selp.b32 %0, 1, 0, p;\n\t}"                                                \
        : "=r"(_done) : "r"(_mbar), "r"(_par) : "memory");                          \
    if (!_done) {                                                                   \
        asm volatile("{\n\t.reg .pred P1;\n\t"                                      \
        "WAIT_LOOP_%=:\n\t"                                                         \
        "mbarrier.try_wait.parity.acquire.cta.shared::cta.b64 P1, [%0], %1, 0x989680;\n\t" \
        "@P1 bra.uni WAIT_DONE_%=;\n\t"                                             \
        "bra.uni WAIT_LOOP_%=;\n\t"                                                 \
        "WAIT_DONE_%=:\n\t}"                                                        \
        :: "r"(_mbar), "r"(_par) : "memory");                                       \
    }                                                                               \
} while (0)

#define TCGEN05_ALLOC(smem_res, ncols) \
    asm volatile("tcgen05.alloc.cta_group::1.sync.aligned.shared::cta.b32 [%0], %1;" \
                 :: "r"((uint32_t)(smem_res)), "r"((uint32_t)(ncols)) : "memory")
#define TCGEN05_DEALLOC(tmem, ncols) \
    asm volatile("tcgen05.dealloc.cta_group::1.sync.aligned.b32 %0, %1;" \
                 :: "r"(tmem), "r"((uint32_t)(ncols)))
#define TCGEN05_RELINQUISH() \
    asm volatile("tcgen05.relinquish_alloc_permit.cta_group::1.sync.aligned;")
#define TCGEN05_COMMIT(mbar) \
    asm volatile("tcgen05.commit.cta_group::1.mbarrier::arrive::one.shared::cluster.b64 [%0];" \
                 :: "r"((uint32_t)(mbar)) : "memory")
#define TCGEN05_FENCE_AFTER() \
    asm volatile("tcgen05.fence::after_thread_sync;" ::: "memory")
#define TCGEN05_FENCE_BEFORE() \
    asm volatile("tcgen05.fence::before_thread_sync;" ::: "memory")
#define TCGEN05_WAIT_LD() \
    asm volatile("tcgen05.wait::ld.sync.aligned;" ::: "memory")

#define BULK_LOAD(dst, src, bytes, mbar) \
    asm volatile("cp.async.bulk.shared::cluster.global.mbarrier::complete_tx::bytes " \
                 "[%0], [%1], %2, [%3];" \
                 :: "r"((uint32_t)(dst)), "l"(src), "r"((uint32_t)(bytes)), \
                    "r"((uint32_t)(mbar)) : "memory")

#define TMA_LOAD_2D(smem_addr, map, cx, cy, mbar) \
    asm volatile( \
        "cp.async.bulk.tensor.2d.shared::cta.global.tile.mbarrier::complete_tx::bytes " \
        "[%0], [%1, {%2, %3}], [%4];" \
        :: "r"((uint32_t)(smem_addr)), "l"(map), "r"((int)(cx)), "r"((int)(cy)), \
           "r"((uint32_t)(mbar)) : "memory")

#define TCGEN05_LD_32X32B_X32(r, tmem_addr) \
    asm volatile( \
        "tcgen05.ld.sync.aligned.32x32b.x32.b32 " \
        "{%0, %1, %2, %3, %4, %5, %6, %7, " \
        " %8, %9, %10, %11, %12, %13, %14, %15, " \
        " %16, %17, %18, %19, %20, %21, %22, %23, " \
        " %24, %25, %26, %27, %28, %29, %30, %31}, [%32];" \
        : "=r"((r)[0]),  "=r"((r)[1]),  "=r"((r)[2]),  "=r"((r)[3]), \
          "=r"((r)[4]),  "=r"((r)[5]),  "=r"((r)[6]),  "=r"((r)[7]), \
          "=r"((r)[8]),  "=r"((r)[9]),  "=r"((r)[10]), "=r"((r)[11]), \
          "=r"((r)[12]), "=r"((r)[13]), "=r"((r)[14]), "=r"((r)[15]), \
          "=r"((r)[16]), "=r"((r)[17]), "=r"((r)[18]), "=r"((r)[19]), \
          "=r"((r)[20]), "=r"((r)[21]), "=r"((r)[22]), "=r"((r)[23]), \
          "=r"((r)[24]), "=r"((r)[25]), "=r"((r)[26]), "=r"((r)[27]), \
          "=r"((r)[28]), "=r"((r)[29]), "=r"((r)[30]), "=r"((r)[31]) \
        : "r"(tmem_addr))

// SW64 K-major smem descriptor: layout 4, version 1, SBO=32, LBO=1.
__device__ __forceinline__ uint64_t make_desc(uint32_t addr) {
    constexpr uint64_t base =
        (uint64_t(4)  << 61) | (uint64_t(1) << 46) |
        (uint64_t(32) << 32) | (uint64_t(1) << 16);
    return base | ((uint64_t)(addr >> 4) & 0x3FFF);
}

__device__ __forceinline__ void mma_bf16(uint32_t d_tmem, uint64_t da, uint64_t db,
                                         uint32_t idesc, uint32_t acc) {
    asm volatile(
        "{\n\t.reg .pred p;\n\tsetp.ne.u32 p, %4, 0;\n\t"
        "tcgen05.mma.cta_group::1.kind::f16 [%0], %1, %2, %3, {%5, %5, %5, %5}, p;\n\t}"
        :: "r"(d_tmem), "l"(da), "l"(db), "r"(idesc), "r"(acc), "r"(0u)
        : "memory");
}
#endif  // HAS_TC

// ---------------------------------------------------------------------------
// GEMM (NT): C = A * B^T, bf16 (hi,lo) planes, 3-pass. Tiles BM=128, BN=256,
// BK=32. 4-stage mbarrier ring (stage 48KB).
//   EPI 0:+bias[n] 1:relu(+bias[n]) 2:*scale 3:+bias[m] 4:none
//   OUT 0: fp32 row-major C   1: bf16 panel planes (Ch, Cl)
//   causal 0:none 1:skip upper tiles 2:K-limit (causal PV)
//   LOADA 1: A via 2D TMA SW64 (row-major probs); else A panels via bulk copy.
//   MERGE 1: blockIdx.z selects operand set from MArgs (independent GEMMs
//            fused into one launch); batch index zz forced to 0.
// ---------------------------------------------------------------------------
static constexpr int SM_TILE0  = 1024;
static constexpr int SM_A_HI   = 0;          // 128x32 bf16 = 8 KB
static constexpr int SM_A_LO   = 8192;
static constexpr int SM_B_HI   = 16384;      // 256x32 bf16 = 16 KB (2 panels)
static constexpr int SM_B_LO   = 32768;
static constexpr int SM_STAGE  = 49152;
static constexpr int GEMM_SMEM = SM_TILE0 + 4 * SM_STAGE;   // 197632 B
static constexpr uint32_t IDESC_BF16 =
    (1u << 4) | (1u << 7) | (1u << 10) | ((256u / 8u) << 17) | ((128u / 16u) << 24);

// Control smem: 0 = tmem ptr, empty[s] = 8+s*8 (s<4), full[s] = 40+s*8.
template<int EPI, int OUT, int LOADA, int MERGE>
__global__ void __launch_bounds__(256, 1)
gemm_tc(const __grid_constant__ CUtensorMap tmAh,
        const __grid_constant__ CUtensorMap tmAl,
        MArgs margs,
        const bf16* __restrict__ Aph0, const bf16* __restrict__ Apl0,
        const bf16* __restrict__ Bph0, const bf16* __restrict__ Bpl0,
        const float* __restrict__ bias0,
        float* __restrict__ C, bf16* __restrict__ Ch0, bf16* __restrict__ Cl0,
        int K, int KAB, int KBB, int ldc,
        int aYoff, int bXoff, int bYoff, long sC, float scale, int causal)
{
    extern __shared__ __align__(1024) char smem[];
    const int tid = threadIdx.x;

    const int rm = blockIdx.y * 128;
    const int cn = blockIdx.x * 256;
    if (causal == 1 && cn > rm + 127) return;

    // Operand selection: merged launches use blockIdx.z as the set index.
    const bf16*  Aph  = Aph0;
    const bf16*  Apl  = Apl0;
    const bf16*  Bph  = Bph0;
    const bf16*  Bpl  = Bpl0;
    const float* bias = bias0;
    bf16* Ch = Ch0;
    bf16* Cl = Cl0;
    int zz = blockIdx.z;
    if (MERGE) {
        const int mi = blockIdx.z;
        Aph = margs.Aph[mi];  Apl = margs.Apl[mi];
        Bph = margs.Bph[mi];  Bpl = margs.Bpl[mi];
        bias = margs.bias[mi];
        Ch = margs.Ch[mi];    Cl = margs.Cl[mi];
        zz = 0;
    }

    if (OUT == 0) C += (long)zz * sC;

    int Keff = K;
    if (causal == 2) Keff = min(K, rm + 128);

#if HAS_TC
    const uint32_t smem_base = smem_u32(smem);
    const int wid = tid >> 5;

    if (tid == 0) {
#pragma unroll
        for (int s = 0; s < 4; s++) {
            MBARRIER_INIT(smem_base + 8 + s * 8, 1);    // empty[s]
            MBARRIER_INIT(smem_base + 40 + s * 8, 1);   // full[s]
        }
    }
    if (wid == 5) TCGEN05_ALLOC(smem_base + 0, 256);
    __syncthreads();

    uint32_t tmem;
    asm volatile("ld.shared.b32 %0, [%1];" : "=r"(tmem) : "r"(smem_base));

    const int NC = Keff >> 5;                 // BK = 32
    const int ay  = zz * aYoff + rm;          // TMA row (LOADA=1)
    const long aP = ((long)((zz * aYoff + rm) >> 7)) * KAB;
    const long bP0 = ((long)((zz * bYoff + cn) >> 7)) * KBB;
    const long bP1 = bP0 + KBB;
    const int  kB0 = (zz * bXoff) >> 5;

    if (wid == 4 && elect_one()) {
        // ---------------- producer (single thread) ----------------
        for (int c = 0; c < NC; c++) {
            const int s = c & 3;
            if (c >= 4)  // stage s still owned by MMA of chunk c-4
                MBARRIER_WAIT_PARITY(smem_base + 8 + s * 8, ((c >> 2) + 1) & 1);
            const uint32_t fullb = smem_base + 40 + s * 8;
            MBARRIER_EXPECT_TX(fullb, (uint32_t)SM_STAGE);
            const uint32_t tn = smem_base + SM_TILE0 + s * SM_STAGE;
            if (LOADA == 1) {
                const int kx = c << 5;
                TMA_LOAD_2D(tn + SM_A_HI, &tmAh, kx, ay, fullb);
                TMA_LOAD_2D(tn + SM_A_LO, &tmAl, kx, ay, fullb);
            } else {
                const long pa = (aP + c) * 8192;
                BULK_LOAD(tn + SM_A_HI, (const char*)Aph + pa, 8192, fullb);
                BULK_LOAD(tn + SM_A_LO, (const char*)Apl + pa, 8192, fullb);
            }
            const long pb0 = (bP0 + kB0 + c) * 8192;
            const long pb1 = (bP1 + kB0 + c) * 8192;
            BULK_LOAD(tn + SM_B_HI,        (const char*)Bph + pb0, 8192, fullb);
            BULK_LOAD(tn + SM_B_HI + 8192, (const char*)Bph + pb1, 8192, fullb);
            BULK_LOAD(tn + SM_B_LO,        (const char*)Bpl + pb0, 8192, fullb);
            BULK_LOAD(tn + SM_B_LO + 8192, (const char*)Bpl + pb1, 8192, fullb);
        }
    } else if (wid == 5 && elect_one()) {
        // ---------------- MMA consumer (single thread) ----------------
        for (int c = 0; c < NC; c++) {
            const int s = c & 3;
            MBARRIER_WAIT_PARITY(smem_base + 40 + s * 8, (c >> 2) & 1);
            const uint32_t tb = smem_base + SM_TILE0 + s * SM_STAGE;
            const uint64_t dah = make_desc(tb + SM_A_HI);
            const uint64_t dal = make_desc(tb + SM_A_LO);
            const uint64_t dbh = make_desc(tb + SM_B_HI);
            const uint64_t dbl = make_desc(tb + SM_B_LO);
#pragma unroll
            for (int st = 0; st < 2; st++)       // hi*hi  (K=16 per step)
                mma_bf16(tmem, dah + st * 2, dbh + st * 2, IDESC_BF16,
                         (c == 0 && st == 0) ? 0u : 1u);
#pragma unroll
            for (int st = 0; st < 2; st++)       // hi*lo
                mma_bf16(tmem, dah + st * 2, dbl + st * 2, IDESC_BF16, 1u);
#pragma unroll
            for (int st = 0; st < 2; st++)       // lo*hi
                mma_bf16(tmem, dal + st * 2, dbh + st * 2, IDESC_BF16, 1u);
            TCGEN05_COMMIT(smem_base + 8 + s * 8);
        }
    }
    // Gate idle/epilogue warps so the tile-final parity wait is unambiguous.
    __syncthreads();

    const int cL = NC - 1;
    MBARRIER_WAIT_PARITY(smem_base + 8 + (cL & 3) * 8, (cL >> 2) & 1);
    TCGEN05_FENCE_AFTER();

    if (wid < 4) {
        const int lane = tid & 31;
        const int m = rm + wid * 32 + lane;
        const float biasm = (EPI == 3) ? bias[m] : 0.f;
#pragma unroll
        for (int seg = 0; seg < 8; seg++) {
            uint32_t r[32];
            TCGEN05_LD_32X32B_X32(r, tmem + seg * 32);
            TCGEN05_WAIT_LD();
#pragma unroll
            for (int j = 0; j < 32; j += 4) {
                float v[4];
#pragma unroll
                for (int tt = 0; tt < 4; tt++) {
                    const int n = cn + seg * 32 + j + tt;
                    float x = __uint_as_float(r[j + tt]);
                    if (EPI == 0)      x += bias[n];
                    else if (EPI == 1) x = fmaxf(x + bias[n], 0.f);
                    else if (EPI == 2) x *= scale;
                    else if (EPI == 3) x += biasm;
                    v[tt] = x;
                }
                if (OUT == 0) {
                    *(float4*)(C + (long)m * ldc + cn + seg * 32 + j) =
                        make_float4(v[0], v[1], v[2], v[3]);
                } else {
                    bf16 h0, l0, h1, l1, h2, l2, h3, l3;
                    bf16_split(v[0], h0, l0); bf16_split(v[1], h1, l1);
                    bf16_split(v[2], h2, l2); bf16_split(v[3], h3, l3);
                    const long off = panel_off(m, cn + seg * 32 + j, ldc);
                    uint2 uh, ul;
                    uh.x = pack2(h0, h1); uh.y = pack2(h2, h3);
                    ul.x = pack2(l0, l1); ul.y = pack2(l2, l3);
                    *(uint2*)((char*)Ch + off) = uh;
                    *(uint2*)((char*)Cl + off) = ul;
                }
            }
        }
        TCGEN05_FENCE_BEFORE();
    }
    __syncthreads();
    if (wid == 5) {
        TCGEN05_RELINQUISH();
        TCGEN05_DEALLOC(tmem, 256);
    }
#else
    // --------------------- SIMT fp32 fallback path -------------------------
    constexpr int BK = 16;
    float (*As)[132] = (float (*)[132])(smem);
    float (*Bs)[132] = (float (*)[132])(smem + BK * 132 * sizeof(float));
    const int tx = tid & 15, ty = tid >> 4;
    const int lda = KAB * 32, ldbK = KBB * 32;

    for (int half = 0; half < 2; half++) {
        const int cnh = cn + half * 128;
        float acc[8][8];
#pragma unroll
        for (int i = 0; i < 8; i++)
#pragma unroll
            for (int j = 0; j < 8; j++) acc[i][j] = 0.f;

        for (int k0 = 0; k0 < Keff; k0 += BK) {
#pragma unroll
            for (int i = 0; i < 2; i++) {
                const int q = i * 256 + tid;
                const int row = q >> 1, kc = (q & 1) * 8;
#pragma unroll
                for (int u = 0; u < 8; u++) {
                    const int k = k0 + kc + u;
                    float av;
                    if (LOADA == 1) {
                        const long ai = (long)(zz * aYoff + rm + row) * lda + k;
                        av = __bfloat162float(Aph[ai]) + __bfloat162float(Apl[ai]);
                    } else {
                        const int gr = zz * aYoff + rm + row;
                        av = panel_read(Aph, gr, k, lda) + panel_read(Apl, gr, k, lda);
                    }
                    const int gbr = zz * bYoff + cnh + row;
                    const int gbk = zz * bXoff + k;
                    As[kc + u][row] = av;
                    Bs[kc + u][row] = panel_read(Bph, gbr, gbk, ldbK) +
                                      panel_read(Bpl, gbr, gbk, ldbK);
                }
            }
            __syncthreads();
#pragma unroll
            for (int kk = 0; kk < BK; kk++) {
                float a[8], b[8];
#pragma unroll
                for (int i = 0; i < 8; i++) a[i] = As[kk][ty * 8 + i];
#pragma unroll
                for (int j = 0; j < 8; j++) b[j] = Bs[kk][tx * 8 + j];
#pragma unroll
                for (int i = 0; i < 8; i++)
#pragma unroll
                    for (int j = 0; j < 8; j++) acc[i][j] += a[i] * b[j];
            }
            __syncthreads();
        }

#pragma unroll
        for (int i = 0; i < 8; i++) {
            const int m = rm + ty * 8 + i;
            const float biasm = (EPI == 3) ? bias[m] : 0.f;
#pragma unroll
            for (int j = 0; j < 8; j++) {
                const int n = cnh + tx * 8 + j;
                float x = acc[i][j];
                if (EPI == 0)      x += bias[n];
                else if (EPI == 1) x = fmaxf(x + bias[n], 0.f);
                else if (EPI == 2) x *= scale;
                else if (EPI == 3) x += biasm;
                if (OUT == 0) C[(long)m * ldc + n] = x;
                else {
                    bf16 hh, ll;
                    bf16_split(x, hh, ll);
                    const long off = panel_off(m, n, ldc);
                    *(bf16*)((char*)Ch + off) = hh;
                    *(bf16*)((char*)Cl + off) = ll;
                }
            }
        }
        __syncthreads();
    }
#endif
}

// ---------------------------------------------------------------------------
// Elementwise bf16 Dekker split -> SW64 PANEL layout.
// ---------------------------------------------------------------------------
__device__ __forceinline__ void split_body(const float* __restrict__ src,
                                           bf16* __restrict__ hi,
                                           bf16* __restrict__ lo, long n4, int kd)
{
    for (long i = blockIdx.x * 256L + threadIdx.x; i < n4; i += (long)gridDim.x * 256) {
        const float4 f = *(const float4*)(src + i * 4);
        bf16 h0, l0, h1, l1, h2, l2, h3, l3;
        bf16_split(f.x, h0, l0); bf16_split(f.y, h1, l1);
        bf16_split(f.z, h2, l2); bf16_split(f.w, h3, l3);
        const long e0 = i * 4;
        const int row = (int)(e0 / kd);
        const int col = (int)(e0 - (long)row * kd);
        const long off = panel_off(row, col, kd);
        uint2 uh, ul;
        uh.x = pack2(h0, h1); uh.y = pack2(h2, h3);
        ul.x = pack2(l0, l1); ul.y = pack2(l2, l3);
        *(uint2*)((char*)hi + off) = uh;
        *(uint2*)((char*)lo + off) = ul;
    }
}

// All 10 input/weight splits fused into one launch (blockIdx.y = tensor).
__global__ void __launch_bounds__(256)
splitN_k(SArgs a)
{
    const int y = blockIdx.y;
    split_body(a.src[y], a.hi[y], a.lo[y], a.n4[y], a.kd[y]);
}

// ---------------------------------------------------------------------------
// Row softmax over fp32 scores -> bf16 (hi, lo) prob planes (row-major).
// ---------------------------------------------------------------------------
__global__ void __launch_bounds__(256)
softmax_k(const float* __restrict__ S, bf16* __restrict__ Ph,
          bf16* __restrict__ Pl, int causal)
{
    const int row = blockIdx.x;
    const int b = row >> 11;
    const int i = row & 2047;
    const float* p = S + (long)b * Sn * Sn + (long)i * Sn;
    bf16* ph = Ph + (long)b * Sn * Sn + (long)i * Sn;
    bf16* pl = Pl + (long)b * Sn * Sn + (long)i * Sn;
    const int L = causal ? (i + 1) : Sn;
    const int FILL = causal ? (((i >> 7) + 1) << 7) : Sn;
    const int tid = threadIdx.x;
    __shared__ float sh[8];

    float m = -3.4e38f;
    for (int j = tid; j < L; j += 256) m = fmaxf(m, p[j]);
#pragma unroll
    for (int o = 16; o > 0; o >>= 1) m = fmaxf(m, __shfl_xor_sync(~0u, m, o));
    if ((tid & 31) == 0) sh[tid >> 5] = m;
    __syncthreads();
    m = sh[0];
#pragma unroll
    for (int w = 1; w < 8; w++) m = fmaxf(m, sh[w]);

    float s = 0.f;
    for (int j = tid; j < L; j += 256) s += __expf(p[j] - m);
#pragma unroll
    for (int o = 16; o > 0; o >>= 1) s += __shfl_xor_sync(~0u, s, o);
    __syncthreads();
    if ((tid & 31) == 0) sh[tid >> 5] = s;
    __syncthreads();
    s = 0.f;
#pragma unroll
    for (int w = 0; w < 8; w++) s += sh[w];
    const float inv = 1.f / s;

    for (int j = tid; j < L; j += 256) {
        const float v = __expf(p[j] - m) * inv;
        bf16 hh, ll;
        bf16_split(v, hh, ll);
        ph[j] = hh;
        pl[j] = ll;
    }
    const bf16 z = __float2bfloat16(0.f);
    for (int j = L + tid; j < FILL; j += 256) { ph[j] = z; pl[j] = z; }
}

// ---------------------------------------------------------------------------
// y = LayerNorm(x + h) * g + b; optional SW64-panel bf16 splits (yh, yl).
// ---------------------------------------------------------------------------
__global__ void __launch_bounds__(256)
add_ln_k(const float* __restrict__ x, const float* __restrict__ h,
         const float* __restrict__ g, const float* __restrict__ bt,
         float* __restrict__ y, bf16* __restrict__ yh, bf16* __restrict__ yl)
{
    const long row = blockIdx.x;
    const float* xr = x + row * En;
    const float* hr = h + row * En;
    const int tid = threadIdx.x;

    float v[3];
    float s = 0.f, s2 = 0.f;
#pragma unroll
    for (int t = 0; t < 3; t++) {
        const int c = tid + t * 256;
        const float u = xr[c] + hr[c];
        v[t] = u;
        s += u;
        s2 += u * u;
    }
    __shared__ float shA[8], shB[8];
#pragma unroll
    for (int o = 16; o > 0; o >>= 1) {
        s  += __shfl_xor_sync(~0u, s,  o);
        s2 += __shfl_xor_sync(~0u, s2, o);
    }
    if ((tid & 31) == 0) { shA[tid >> 5] = s; shB[tid >> 5] = s2; }
    __syncthreads();
    s = 0.f; s2 = 0.f;
#pragma unroll
    for (int w = 0; w < 8; w++) { s += shA[w]; s2 += shB[w]; }

    const float mu   = s * (1.f / En);
    const float var  = s2 * (1.f / En) - mu * mu;
    const float rstd = rsqrtf(var + LNEPS);
#pragma unroll
    for (int t = 0; t < 3; t++) {
        const int c = tid + t * 256;
        const float o = (v[t] - mu) * rstd * g[c] + bt[c];
        y[row * En + c] = o;
        if (yh) {
            bf16 hh, ll;
            bf16_split(o, hh, ll);
            const long off = panel_off((int)row, c, En);
            *(bf16*)((char*)yh + off) = hh;
            *(bf16*)((char*)yl + off) = ll;
        }
    }
}

// ---------------------------------------------------------------------------
// Host: tensor-map encoding (probs only; SW64, box {32, boxRows}).
// ---------------------------------------------------------------------------
typedef CUresult (*PFN_tmEncode)(
    CUtensorMap*, CUtensorMapDataType, cuuint32_t, void*,
    const cuuint64_t*, const cuuint64_t*, const cuuint32_t*, const cuuint32_t*,
    CUtensorMapInterleave, CUtensorMapSwizzle, CUtensorMapL2promotion,
    CUtensorMapFloatOOBfill);

static PFN_tmEncode tm_encoder() {
    static PFN_tmEncode fn = nullptr;
    if (!fn) {
        void* p = nullptr;
        cudaDriverEntryPointQueryResult st;
#if CUDART_VERSION >= 12050
        cudaGetDriverEntryPointByVersion("cuTensorMapEncodeTiled", &p, 12000,
                                         cudaEnableDefault, &st);
#else
        cudaGetDriverEntryPoint("cuTensorMapEncodeTiled", &p,
                                cudaEnableDefault, &st);
#endif
        fn = (PFN_tmEncode)p;
    }
    return fn;
}

static CUtensorMap make_map(const void* base, long rowElems, long nRows, int boxRows)
{
    CUtensorMap m;
    cuuint64_t dims[2]    = {(cuuint64_t)rowElems, (cuuint64_t)nRows};
    cuuint64_t strides[1] = {(cuuint64_t)rowElems * 2};
    cuuint32_t box[2]     = {32u, (cuuint32_t)boxRows};
    cuuint32_t es[2]      = {1u, 1u};
    tm_encoder()(&m, CU_TENSOR_MAP_DATA_TYPE_BFLOAT16, 2, (void*)base,
                 dims, strides, box, es,
                 CU_TENSOR_MAP_INTERLEAVE_NONE, CU_TENSOR_MAP_SWIZZLE_64B,
                 CU_TENSOR_MAP_L2_PROMOTION_L2_128B,
                 CU_TENSOR_MAP_FLOAT_OOB_FILL_NONE);
    return m;
}

// ---------------------------------------------------------------------------
// Host launcher
// ---------------------------------------------------------------------------
extern "C" void kernel_launch(void* const* d_in, const int* in_sizes, int n_in,
                              void* d_out, int out_size)
{
    const float* x     = (const float*)d_in[0];
    const float* kv    = (const float*)d_in[1];
    const float* wq_w  = (const float*)d_in[2];
    const float* wq_b  = (const float*)d_in[3];
    const float* wk_w  = (const float*)d_in[4];
    const float* wk_b  = (const float*)d_in[5];
    const float* wv_w  = (const float*)d_in[6];
    const float* wv_b  = (const float*)d_in[7];
    const float* ln1_g = (const float*)d_in[8];
    const float* ln1_b = (const float*)d_in[9];
    const float* wq2_w = (const float*)d_in[10];
    const float* wq2_b = (const float*)d_in[11];
    const float* wk2_w = (const float*)d_in[12];
    const float* wk2_b = (const float*)d_in[13];
    const float* wv2_w = (const float*)d_in[14];
    const float* wv2_b = (const float*)d_in[15];
    const float* ln2_g = (const float*)d_in[16];
    const float* ln2_b = (const float*)d_in[17];
    const float* w1    = (const float*)d_in[18];
    const float* b1    = (const float*)d_in[19];
    const float* w2    = (const float*)d_in[20];
    const float* b2    = (const float*)d_in[21];
    const float* ln3_g = (const float*)d_in[22];
    const float* ln3_b = (const float*)d_in[23];
    float* out = (float*)d_out;

    bf16 *qh, *ql, *kh, *kl, *k2h, *k2l, *vth, *vtl, *vt2h, *vt2l;
    bf16 *prh, *prl, *hh, *hl, *x1h, *x1l, *x2h, *x2l, *xh, *xl, *kvh, *kvl, *wh, *wl;
    float *ps, *phf, *x1, *x2, *pmlp;
    cudaGetSymbolAddress((void**)&qh,  g_qh);   cudaGetSymbolAddress((void**)&ql,  g_ql);
    cudaGetSymbolAddress((void**)&kh,  g_kh);   cudaGetSymbolAddress((void**)&kl,  g_kl);
    cudaGetSymbolAddress((void**)&k2h, g_k2h);  cudaGetSymbolAddress((void**)&k2l, g_k2l);
    cudaGetSymbolAddress((void**)&vth, g_vth);  cudaGetSymbolAddress((void**)&vtl, g_vtl);
    cudaGetSymbolAddress((void**)&vt2h, g_vt2h); cudaGetSymbolAddress((void**)&vt2l, g_vt2l);
    cudaGetSymbolAddress((void**)&prh, g_ph);   cudaGetSymbolAddress((void**)&prl, g_pl);
    cudaGetSymbolAddress((void**)&hh,  g_hh);   cudaGetSymbolAddress((void**)&hl,  g_hl);
    cudaGetSymbolAddress((void**)&x1h, g_x1h);  cudaGetSymbolAddress((void**)&x1l, g_x1l);
    cudaGetSymbolAddress((void**)&x2h, g_x2h);  cudaGetSymbolAddress((void**)&x2l, g_x2l);
    cudaGetSymbolAddress((void**)&xh,  g_xh);   cudaGetSymbolAddress((void**)&xl,  g_xl);
    cudaGetSymbolAddress((void**)&kvh, g_kvh);  cudaGetSymbolAddress((void**)&kvl, g_kvl);
    cudaGetSymbolAddress((void**)&wh,  g_wh);   cudaGetSymbolAddress((void**)&wl,  g_wl);
    cudaGetSymbolAddress((void**)&ps,  g_s);
    cudaGetSymbolAddress((void**)&phf, g_h);
    cudaGetSymbolAddress((void**)&x1,  g_x1);
    cudaGetSymbolAddress((void**)&x2,  g_x2);
    cudaGetSymbolAddress((void**)&pmlp, g_mlp);

    const long oWQ = 0, oWK = oWQ + (long)En * En, oWV = oWK + (long)En * En;
    const long oWQ2 = oWV + (long)En * En, oWK2 = oWQ2 + (long)En * En;
    const long oWV2 = oWK2 + (long)En * En;
    const long oW1 = oWV2 + (long)En * En, oW2 = oW1 + (long)DFFn * En;

    cudaFuncSetAttribute(gemm_tc<0,1,0,1>, cudaFuncAttributeMaxDynamicSharedMemorySize, GEMM_SMEM);
    cudaFuncSetAttribute(gemm_tc<3,1,0,1>, cudaFuncAttributeMaxDynamicSharedMemorySize, GEMM_SMEM);
    cudaFuncSetAttribute(gemm_tc<0,1,0,0>, cudaFuncAttributeMaxDynamicSharedMemorySize, GEMM_SMEM);
    cudaFuncSetAttribute(gemm_tc<2,0,0,0>, cudaFuncAttributeMaxDynamicSharedMemorySize, GEMM_SMEM);
    cudaFuncSetAttribute(gemm_tc<4,0,1,0>, cudaFuncAttributeMaxDynamicSharedMemorySize, GEMM_SMEM);
    cudaFuncSetAttribute(gemm_tc<1,1,0,0>, cudaFuncAttributeMaxDynamicSharedMemorySize, GEMM_SMEM);
    cudaFuncSetAttribute(gemm_tc<1,0,0,0>, cudaFuncAttributeMaxDynamicSharedMemorySize, GEMM_SMEM);

    const float scale = 0.03608439182435161f;  // 1/sqrt(768)
    const long sSS = (long)Sn * Sn;
    const long sQE = (long)Sn * En;

    const dim3 gQKK2(En / 256, MTOT / 128, 3);       // merged Q, K, K2
    const dim3 gVT2(MTOT / 256, En / 128, 2);        // merged V^T, V2^T
    const dim3 gProj(En / 256, MTOT / 128, 1);       // Q2
    const dim3 gScore(Sn / 256, Sn / 128, Bn);
    const dim3 gPV(En / 256, Sn / 128, Bn);
    const dim3 gFF1(DFFn / 256, MTOT / 128, 1);
    const dim3 gFF2(En / 256, MTOT / 128, 1);

    const long nXY = (long)MTOT * En / 4;
    const long nW  = (long)En * En / 4;
    const long nFF = (long)DFFn * En / 4;

    CUtensorMap mPh = make_map(prh, Sn, MTOT, 128);
    CUtensorMap mPl = make_map(prl, Sn, MTOT, 128);

    MArgs m0{};                                      // unused slots for non-merged

    // All 10 splits in one launch.
    SArgs sa{};
    sa.src[0] = x;     sa.hi[0] = xh;        sa.lo[0] = xl;        sa.n4[0] = nXY; sa.kd[0] = En;
    sa.src[1] = kv;    sa.hi[1] = kvh;       sa.lo[1] = kvl;       sa.n4[1] = nXY; sa.kd[1] = En;
    sa.src[2] = wq_w;  sa.hi[2] = wh + oWQ;  sa.lo[2] = wl + oWQ;  sa.n4[2] = nW;  sa.kd[2] = En;
    sa.src[3] = wk_w;  sa.hi[3] = wh + oWK;  sa.lo[3] = wl + oWK;  sa.n4[3] = nW;  sa.kd[3] = En;
    sa.src[4] = wv_w;  sa.hi[4] = wh + oWV;  sa.lo[4] = wl + oWV;  sa.n4[4] = nW;  sa.kd[4] = En;
    sa.src[5] = wq2_w; sa.hi[5] = wh + oWQ2; sa.lo[5] = wl + oWQ2; sa.n4[5] = nW;  sa.kd[5] = En;
    sa.src[6] = wk2_w; sa.hi[6] = wh + oWK2; sa.lo[6] = wl + oWK2; sa.n4[6] = nW;  sa.kd[6] = En;
    sa.src[7] = wv2_w; sa.hi[7] = wh + oWV2; sa.lo[7] = wl + oWV2; sa.n4[7] = nW;  sa.kd[7] = En;
    sa.src[8] = w1;    sa.hi[8] = wh + oW1;  sa.lo[8] = wl + oW1;  sa.n4[8] = nFF; sa.kd[8] = En;
    sa.src[9] = w2;    sa.hi[9] = wh + oW2;  sa.lo[9] = wl + oW2;  sa.n4[9] = nFF; sa.kd[9] = DFFn;
    splitN_k<<<dim3(592, 10), 256>>>(sa);

    // Merged Q / K / K2 projections (z selects operand set).
    MArgs mp{};
    mp.Aph[0] = xh;  mp.Apl[0] = xl;  mp.Bph[0] = wh + oWQ;  mp.Bpl[0] = wl + oWQ;
    mp.bias[0] = wq_b;  mp.Ch[0] = qh;  mp.Cl[0] = ql;
    mp.Aph[1] = xh;  mp.Apl[1] = xl;  mp.Bph[1] = wh + oWK;  mp.Bpl[1] = wl + oWK;
    mp.bias[1] = wk_b;  mp.Ch[1] = kh;  mp.Cl[1] = kl;
    mp.Aph[2] = kvh; mp.Apl[2] = kvl; mp.Bph[2] = wh + oWK2; mp.Bpl[2] = wl + oWK2;
    mp.bias[2] = wk2_b; mp.Ch[2] = k2h; mp.Cl[2] = k2l;
    gemm_tc<0,1,0,1><<<gQKK2, 256, GEMM_SMEM>>>(mPh, mPl, mp,
        nullptr, nullptr, nullptr, nullptr, nullptr, nullptr, nullptr, nullptr,
        En, 24, 24, En, 0, 0, 0, 0, 1.f, 0);

    // Merged V^T / V2^T (A = weight panels, B = activations, bias over rows).
    MArgs mv{};
    mv.Aph[0] = wh + oWV;  mv.Apl[0] = wl + oWV;  mv.Bph[0] = xh;  mv.Bpl[0] = xl;
    mv.bias[0] = wv_b;  mv.Ch[0] = vth;  mv.Cl[0] = vtl;
    mv.Aph[1] = wh + oWV2; mv.Apl[1] = wl + oWV2; mv.Bph[1] = kvh; mv.Bpl[1] = kvl;
    mv.bias[1] = wv2_b; mv.Ch[1] = vt2h; mv.Cl[1] = vt2l;
    mv.Aph[2] = mv.Aph[0]; mv.Apl[2] = mv.Apl[0]; mv.Bph[2] = mv.Bph[0];
    mv.Bpl[2] = mv.Bpl[0]; mv.bias[2] = mv.bias[0]; mv.Ch[2] = mv.Ch[0]; mv.Cl[2] = mv.Cl[0];
    gemm_tc<3,1,0,1><<<gVT2, 256, GEMM_SMEM>>>(mPh, mPl, mv,
        nullptr, nullptr, nullptr, nullptr, nullptr, nullptr, nullptr, nullptr,
        En, 24, 24, MTOT, 0, 0, 0, 0, 1.f, 0);

    // ---- causal self-attention ----
    gemm_tc<2,0,0,0><<<gScore, 256, GEMM_SMEM>>>(mPh, mPl, m0,
        qh, ql, kh, kl, nullptr, ps, nullptr, nullptr,
        En, 24, 24, Sn, Sn, 0, Sn, sSS, scale, 1);
    softmax_k<<<MTOT, 256>>>(ps, prh, prl, 1);
    gemm_tc<4,0,1,0><<<gPV, 256, GEMM_SMEM>>>(mPh, mPl, m0,
        prh, prl, vth, vtl, nullptr, phf, nullptr, nullptr,
        Sn, 64, 256, En, Sn, Sn, 0, sQE, 1.f, 2);
    add_ln_k<<<MTOT, 256>>>(x, phf, ln1_g, ln1_b, x1, x1h, x1l);

    // ---- cross-attention (K2 / V2^T already computed) ----
    gemm_tc<0,1,0,0><<<gProj, 256, GEMM_SMEM>>>(mPh, mPl, m0,
        x1h, x1l, wh + oWQ2, wl + oWQ2, wq2_b, nullptr, qh, ql,
        En, 24, 24, En, 0, 0, 0, 0, 1.f, 0);
    gemm_tc<2,0,0,0><<<gScore, 256, GEMM_SMEM>>>(mPh, mPl, m0,
        qh, ql, k2h, k2l, nullptr, ps, nullptr, nullptr,
        En, 24, 24, Sn, Sn, 0, Sn, sSS, scale, 0);
    softmax_k<<<MTOT, 256>>>(ps, prh, prl, 0);
    gemm_tc<4,0,1,0><<<gPV, 256, GEMM_SMEM>>>(mPh, mPl, m0,
        prh, prl, vt2h, vt2l, nullptr, phf, nullptr, nullptr,
        Sn, 64, 256, En, Sn, Sn, 0, sQE, 1.f, 0);
    add_ln_k<<<MTOT, 256>>>(x1, phf, ln2_g, ln2_b, x2, x2h, x2l);

    // ---- MLP ----
    gemm_tc<1,1,0,0><<<gFF1, 256, GEMM_SMEM>>>(mPh, mPl, m0,
        x2h, x2l, wh + oW1, wl + oW1, b1, nullptr, hh, hl,
        En, 24, 24, DFFn, 0, 0, 0, 0, 1.f, 0);
    gemm_tc<1,0,0,0><<<gFF2, 256, GEMM_SMEM>>>(mPh, mPl, m0,
        hh, hl, wh + oW2, wl + oW2, b2, pmlp, nullptr, nullptr,
        DFFn, 96, 96, En, 0, 0, 0, 0, 1.f, 0);
    add_ln_k<<<MTOT, 256>>>(x2, pmlp, ln3_g, ln3_b, out, nullptr, nullptr);
}